// round 6
// baseline (speedup 1.0000x reference)
#include <cuda_runtime.h>
#include <math.h>
#include <stdint.h>

#define Bc 2
#define Sc 2048
#define Ec 1024
#define Hc 16
#define Dc 64
#define Fc 4096
#define Mc (Bc*Sc)          // 4096 rows
#define MB (1024*1024)

// ---------------- scratch (no cudaMalloc allowed) ----------------
__device__ float g_n  [Mc*Ec];
__device__ float g_q  [Mc*Ec];
__device__ float g_k  [Mc*Ec];
__device__ float g_v  [Mc*Ec];
__device__ float g_ctx[Mc*Ec];
__device__ float g_res[Mc*Ec];
__device__ float g_x2 [Mc*Ec];
__device__ float g_f1 [Mc*Fc];
__device__ float g_wr [12*MB];   // tf32-rounded weights: Wq,Wk,Wv,Wo (1M ea), W1 (4M), W2 (4M)

// ---------------- helpers ----------------
__device__ __forceinline__ uint32_t f2tf(float f) {
    uint32_t u;
    asm("cvt.rna.tf32.f32 %0, %1;" : "=r"(u) : "f"(f));
    return u;
}
__device__ __forceinline__ float rtf(float f) { return __uint_as_float(f2tf(f)); }

__device__ __forceinline__ void mma8(float* c, const uint32_t* a, const uint32_t* b) {
    asm volatile(
        "mma.sync.aligned.m16n8k8.row.col.f32.tf32.tf32.f32 "
        "{%0,%1,%2,%3}, {%4,%5,%6,%7}, {%8,%9}, {%0,%1,%2,%3};\n"
        : "+f"(c[0]), "+f"(c[1]), "+f"(c[2]), "+f"(c[3])
        : "r"(a[0]), "r"(a[1]), "r"(a[2]), "r"(a[3]),
          "r"(b[0]), "r"(b[1]));
}

__device__ __forceinline__ void cp16(uint32_t dst, const float* src) {
    asm volatile("cp.async.cg.shared.global [%0], [%1], 16;" :: "r"(dst), "l"(src));
}
#define CP_COMMIT() asm volatile("cp.async.commit_group;")
#define CP_WAIT0()  asm volatile("cp.async.wait_group 0;")
#define CP_WAIT1()  asm volatile("cp.async.wait_group 1;")

// ---------------- fused weight-rounding: all 6 matrices, one launch ----------------
__global__ void __launch_bounds__(256) round_all(const float* __restrict__ Wq,
                                                 const float* __restrict__ Wk,
                                                 const float* __restrict__ Wv,
                                                 const float* __restrict__ Wo,
                                                 const float* __restrict__ W1,
                                                 const float* __restrict__ W2,
                                                 float* __restrict__ dst) {
    long i4 = (long)blockIdx.x * 256 + threadIdx.x;   // float4 index, 3M total
    long fi = i4 * 4;
    const float* src;
    if      (fi <  1*MB) src = Wq + fi;
    else if (fi <  2*MB) src = Wk + (fi - 1*MB);
    else if (fi <  3*MB) src = Wv + (fi - 2*MB);
    else if (fi <  4*MB) src = Wo + (fi - 3*MB);
    else if (fi <  8*MB) src = W1 + (fi - 4*MB);
    else                 src = W2 + (fi - 8*MB);
    float4 f = *(const float4*)src;
    f.x = rtf(f.x); f.y = rtf(f.y); f.z = rtf(f.z); f.w = rtf(f.w);
    *(float4*)(dst + fi) = f;
}

// ---------------- LayerNorm ----------------
template<bool RND>
__global__ void __launch_bounds__(256) ln_kernel(const float* __restrict__ x,
                                                 const float* __restrict__ g,
                                                 const float* __restrict__ b,
                                                 float* __restrict__ out) {
    int row = blockIdx.x;
    int tid = threadIdx.x;
    const float4* xr = (const float4*)(x + (size_t)row * Ec);
    float4 xv = xr[tid];
    float s  = xv.x + xv.y + xv.z + xv.w;
    float sq = xv.x*xv.x + xv.y*xv.y + xv.z*xv.z + xv.w*xv.w;
    #pragma unroll
    for (int o = 16; o; o >>= 1) {
        s  += __shfl_xor_sync(0xffffffffu, s,  o);
        sq += __shfl_xor_sync(0xffffffffu, sq, o);
    }
    __shared__ float ws[8], wq[8];
    __shared__ float s_mu, s_rstd;
    int lane = tid & 31, wid = tid >> 5;
    if (lane == 0) { ws[wid] = s; wq[wid] = sq; }
    __syncthreads();
    if (tid == 0) {
        float S = 0.f, Q = 0.f;
        #pragma unroll
        for (int i = 0; i < 8; i++) { S += ws[i]; Q += wq[i]; }
        float mu  = S * (1.0f / Ec);
        float var = Q * (1.0f / Ec) - mu * mu;
        s_mu = mu;
        s_rstd = rsqrtf(var + 1e-5f);
    }
    __syncthreads();
    float mu = s_mu, rstd = s_rstd;
    float4 gv = ((const float4*)g)[tid];
    float4 bv = ((const float4*)b)[tid];
    float4 ov;
    ov.x = (xv.x - mu) * rstd * gv.x + bv.x;
    ov.y = (xv.y - mu) * rstd * gv.y + bv.y;
    ov.z = (xv.z - mu) * rstd * gv.z + bv.z;
    ov.w = (xv.w - mu) * rstd * gv.w + bv.w;
    if (RND) { ov.x = rtf(ov.x); ov.y = rtf(ov.y); ov.z = rtf(ov.z); ov.w = rtf(ov.w); }
    ((float4*)(out + (size_t)row * Ec))[tid] = ov;
}

// ---------------- tf32 TC GEMM: 128x128x32, 8 warps, 3-stage cp.async ----------------
enum { EP_PLAIN = 0, EP_HEADS = 1, EP_RES = 2, EP_GELU = 3 };

#define BM 128
#define BN 128
#define BK 32
#define LDA 36      // bank = (4m + c) % 32 conflict-free
#define LDB 136     // bank = (8c + n) % 32 conflict-free
#define STG_A (BM * LDA)            // 4608 floats
#define STG_B (BK * LDB)            // 4352 floats
#define STG   (STG_A + STG_B)       // 8960 floats
#define NSTAGE 3
#define TG_SMEM (NSTAGE * STG * 4)  // 107520 bytes

template<int EP>
__global__ void __launch_bounds__(256, 2) tgemm(const float* __restrict__ A,
                                                const float* __restrict__ W,
                                                const float* __restrict__ bias,
                                                const float* __restrict__ res,
                                                float* __restrict__ C,
                                                int M, int N, int K) {
    extern __shared__ float sh[];
    uint32_t smem_u = (uint32_t)__cvta_generic_to_shared(sh);

    int tid  = threadIdx.x;
    int lane = tid & 31;
    int w    = tid >> 5;
    int wm   = (w & 3) * 32;
    int wn   = (w >> 2) * 64;
    int row0 = blockIdx.y * BM;
    int col0 = blockIdx.x * BN;

    const float* Ab = A + (size_t)row0 * K;
    const float* Wb = W + col0;

    int ar  = tid >> 3, akc = (tid & 7) * 4;   // + i*32 rows
    int bkr = tid >> 5, bnc = (tid & 31) * 4;  // + i*8 rows

    auto issue = [&](int k0, int s) {
        uint32_t sa = smem_u + (uint32_t)(s * STG) * 4u;
        uint32_t sb = sa + (uint32_t)STG_A * 4u;
        #pragma unroll
        for (int i = 0; i < 4; i++) {
            int r = ar + i * 32;
            cp16(sa + (uint32_t)(r * LDA + akc) * 4u, Ab + (size_t)r * K + k0 + akc);
            int kr = bkr + i * 8;
            cp16(sb + (uint32_t)(kr * LDB + bnc) * 4u, Wb + (size_t)(k0 + kr) * N + bnc);
        }
        CP_COMMIT();
    };

    float acc[2][8][4];
    #pragma unroll
    for (int mi = 0; mi < 2; mi++)
        #pragma unroll
        for (int ni = 0; ni < 8; ni++)
            #pragma unroll
            for (int q = 0; q < 4; q++) acc[mi][ni][q] = 0.f;

    int nk = K / BK;
    issue(0, 0);
    issue(BK, 1);

    int r_ = lane >> 2, c_ = lane & 3;
    int st = 0;
    for (int kt = 0; kt < nk; kt++) {
        if (kt + 1 < nk) { CP_WAIT1(); } else { CP_WAIT0(); }
        __syncthreads();
        if (kt + 2 < nk) {
            int s2 = st + 2; if (s2 >= NSTAGE) s2 -= NSTAGE;
            issue((kt + 2) * BK, s2);
        }

        const uint32_t* Sa = (const uint32_t*)(sh + st * STG);
        const uint32_t* Sb = Sa + STG_A;

        #pragma unroll
        for (int ks = 0; ks < 4; ks++) {
            int kb = ks * 8;
            uint32_t af[2][4], bf[8][2];
            #pragma unroll
            for (int mi = 0; mi < 2; mi++) {
                int m = wm + mi * 16 + r_;
                af[mi][0] = Sa[m * LDA + kb + c_];
                af[mi][1] = Sa[(m + 8) * LDA + kb + c_];
                af[mi][2] = Sa[m * LDA + kb + c_ + 4];
                af[mi][3] = Sa[(m + 8) * LDA + kb + c_ + 4];
            }
            #pragma unroll
            for (int ni = 0; ni < 8; ni++) {
                int n = wn + ni * 8 + r_;
                bf[ni][0] = Sb[(kb + c_) * LDB + n];
                bf[ni][1] = Sb[(kb + c_ + 4) * LDB + n];
            }
            #pragma unroll
            for (int mi = 0; mi < 2; mi++)
                #pragma unroll
                for (int ni = 0; ni < 8; ni++)
                    mma8(acc[mi][ni], af[mi], bf[ni]);
        }
        if (++st == NSTAGE) st = 0;
    }

    // ---- epilogue ----
    int c2 = (lane & 3) * 2;
    #pragma unroll
    for (int mi = 0; mi < 2; mi++) {
        #pragma unroll
        for (int ni = 0; ni < 8; ni++) {
            #pragma unroll
            for (int h = 0; h < 2; h++) {
                int row = row0 + wm + mi * 16 + r_ + h * 8;
                int col = col0 + wn + ni * 8 + c2;
                float v0 = acc[mi][ni][h * 2 + 0] + bias[col];
                float v1 = acc[mi][ni][h * 2 + 1] + bias[col + 1];
                if (EP == EP_GELU) {
                    v0 = 0.5f * v0 * (1.f + erff(v0 * 0.70710678118654752f));
                    v1 = 0.5f * v1 * (1.f + erff(v1 * 0.70710678118654752f));
                }
                if (EP == EP_RES) {
                    v0 += res[(size_t)row * N + col];
                    v1 += res[(size_t)row * N + col + 1];
                }
                if (EP == EP_HEADS || EP == EP_GELU) { v0 = rtf(v0); v1 = rtf(v1); }
                if (EP == EP_HEADS) {
                    int bb = row >> 11, ss = row & 2047;
                    int hh = col >> 6,  dd = col & 63;
                    *(float2*)&C[(((size_t)(bb * Hc + hh)) * Sc + ss) * Dc + dd] =
                        make_float2(v0, v1);
                } else {
                    *(float2*)&C[(size_t)row * N + col] = make_float2(v0, v1);
                }
            }
        }
    }
}

// ---------------- tf32 TC flash attention: Q-tile 128, 8 warps, cp.async KV ----------------
#define QT 128
#define LDK 68
#define LDV 72
#define LDP 68
#define KV_STG (64*LDK + 64*LDV)                   // floats per stage
#define ATTN_SMEM ((2*KV_STG + QT*LDP) * 4)        // 106496 bytes

__global__ void __launch_bounds__(256, 2) attn_tc(const float* __restrict__ Q,
                                                  const float* __restrict__ K,
                                                  const float* __restrict__ V,
                                                  float* __restrict__ ctx) {
    extern __shared__ uint32_t smu[];
    uint32_t smem_u = (uint32_t)__cvta_generic_to_shared(smu);
    uint32_t* Ps = smu + 2 * KV_STG;

    int tid = threadIdx.x, lane = tid & 31, w = tid >> 5;
    int r_ = lane >> 2, c_ = lane & 3;
    int qt = (int)gridDim.x - 1 - (int)blockIdx.x;   // heavy tiles first
    int bh = blockIdx.y;
    int q0 = qt * QT;
    int nkv = 2 * qt + 2;                             // 64-wide kv tiles

    const float* Qb = Q + (size_t)bh * Sc * Dc;
    const float* Kb = K + (size_t)bh * Sc * Dc;
    const float* Vb = V + (size_t)bh * Sc * Dc;

    auto issue_kv = [&](int k0, int s) {
        uint32_t kb_ = smem_u + (uint32_t)(s * KV_STG) * 4u;
        uint32_t vb_ = kb_ + (uint32_t)(64 * LDK) * 4u;
        #pragma unroll
        for (int it = 0; it < 4; it++) {
            int idx = tid + it * 256;
            int r = idx >> 4, d4 = (idx & 15) * 4;
            cp16(kb_ + (uint32_t)(r * LDK + d4) * 4u, Kb + (size_t)(k0 + r) * Dc + d4);
            cp16(vb_ + (uint32_t)(r * LDV + d4) * 4u, Vb + (size_t)(k0 + r) * Dc + d4);
        }
        CP_COMMIT();
    };

    issue_kv(0, 0);

    // ---- stage Q (pre-scaled) into Ps, then per-warp A-frags into regs ----
    #pragma unroll
    for (int it = 0; it < 8; it++) {
        int idx = tid + it * 256;
        int r = idx >> 4, d4 = (idx & 15) * 4;
        float4 f = *(const float4*)(Qb + (size_t)(q0 + r) * Dc + d4);
        Ps[r * LDP + d4 + 0] = __float_as_uint(f.x * 0.125f);
        Ps[r * LDP + d4 + 1] = __float_as_uint(f.y * 0.125f);
        Ps[r * LDP + d4 + 2] = __float_as_uint(f.z * 0.125f);
        Ps[r * LDP + d4 + 3] = __float_as_uint(f.w * 0.125f);
    }
    __syncthreads();
    uint32_t qf[8][4];
    {
        const uint32_t* pw0 = Ps + w * 16 * LDP;
        #pragma unroll
        for (int kc = 0; kc < 8; kc++) {
            int kb = kc * 8;
            qf[kc][0] = pw0[r_ * LDP + kb + c_];
            qf[kc][1] = pw0[(r_ + 8) * LDP + kb + c_];
            qf[kc][2] = pw0[r_ * LDP + kb + c_ + 4];
            qf[kc][3] = pw0[(r_ + 8) * LDP + kb + c_ + 4];
        }
    }

    float o[8][4];
    #pragma unroll
    for (int nf = 0; nf < 8; nf++)
        #pragma unroll
        for (int q = 0; q < 4; q++) o[nf][q] = 0.f;
    float m0 = -1e30f, m1 = -1e30f, l0 = 0.f, l1 = 0.f;

    uint32_t* pw = Ps + w * 16 * LDP;
    int rr0 = q0 + w * 16 + r_;     // this thread's global q rows
    int rr1 = rr0 + 8;

    for (int kt = 0; kt < nkv; kt++) {
        int k0 = kt * 64;
        CP_WAIT0();
        __syncthreads();
        if (kt + 1 < nkv) issue_kv((kt + 1) * 64, (kt + 1) & 1);

        const uint32_t* Ks = smu + (kt & 1) * KV_STG;
        const uint32_t* Vs = Ks + 64 * LDK;

        // ---- S = (Q/8) K^T ----
        float sacc[8][4];
        #pragma unroll
        for (int nf = 0; nf < 8; nf++)
            #pragma unroll
            for (int q = 0; q < 4; q++) sacc[nf][q] = 0.f;
        #pragma unroll
        for (int kc = 0; kc < 8; kc++) {
            int kb = kc * 8;
            #pragma unroll
            for (int nf = 0; nf < 8; nf++) {
                uint32_t b[2];
                b[0] = Ks[(nf * 8 + r_) * LDK + kb + c_];
                b[1] = Ks[(nf * 8 + r_) * LDK + kb + c_ + 4];
                mma8(sacc[nf], qf[kc], b);
            }
        }

        // ---- causal mask (global coords), only when tile can cross diagonal ----
        if (k0 + 63 > q0 + w * 16) {
            #pragma unroll
            for (int nf = 0; nf < 8; nf++) {
                int cc = k0 + nf * 8 + 2 * c_;
                if (cc     > rr0) sacc[nf][0] = -1e30f;
                if (cc + 1 > rr0) sacc[nf][1] = -1e30f;
                if (cc     > rr1) sacc[nf][2] = -1e30f;
                if (cc + 1 > rr1) sacc[nf][3] = -1e30f;
            }
        }

        // ---- online softmax ----
        float mx0 = -1e30f, mx1 = -1e30f;
        #pragma unroll
        for (int nf = 0; nf < 8; nf++) {
            mx0 = fmaxf(mx0, fmaxf(sacc[nf][0], sacc[nf][1]));
            mx1 = fmaxf(mx1, fmaxf(sacc[nf][2], sacc[nf][3]));
        }
        mx0 = fmaxf(mx0, __shfl_xor_sync(0xffffffffu, mx0, 1));
        mx0 = fmaxf(mx0, __shfl_xor_sync(0xffffffffu, mx0, 2));
        mx1 = fmaxf(mx1, __shfl_xor_sync(0xffffffffu, mx1, 1));
        mx1 = fmaxf(mx1, __shfl_xor_sync(0xffffffffu, mx1, 2));
        float mn0 = fmaxf(m0, mx0), mn1 = fmaxf(m1, mx1);
        float es0 = __expf(m0 - mn0), es1 = __expf(m1 - mn1);
        m0 = mn0; m1 = mn1;
        float ls0 = 0.f, ls1 = 0.f;
        #pragma unroll
        for (int nf = 0; nf < 8; nf++) {
            sacc[nf][0] = __expf(sacc[nf][0] - mn0);
            sacc[nf][1] = __expf(sacc[nf][1] - mn0);
            sacc[nf][2] = __expf(sacc[nf][2] - mn1);
            sacc[nf][3] = __expf(sacc[nf][3] - mn1);
            ls0 += sacc[nf][0] + sacc[nf][1];
            ls1 += sacc[nf][2] + sacc[nf][3];
        }
        ls0 += __shfl_xor_sync(0xffffffffu, ls0, 1);
        ls0 += __shfl_xor_sync(0xffffffffu, ls0, 2);
        ls1 += __shfl_xor_sync(0xffffffffu, ls1, 1);
        ls1 += __shfl_xor_sync(0xffffffffu, ls1, 2);
        l0 = l0 * es0 + ls0;
        l1 = l1 * es1 + ls1;
        #pragma unroll
        for (int nf = 0; nf < 8; nf++) {
            o[nf][0] *= es0; o[nf][1] *= es0;
            o[nf][2] *= es1; o[nf][3] *= es1;
        }

        // ---- P to warp-private smem, C-frag -> A-frag reshape ----
        #pragma unroll
        for (int nf = 0; nf < 8; nf++) {
            int cb = nf * 8 + 2 * c_;
            pw[r_ * LDP + cb]           = __float_as_uint(sacc[nf][0]);
            pw[r_ * LDP + cb + 1]       = __float_as_uint(sacc[nf][1]);
            pw[(r_ + 8) * LDP + cb]     = __float_as_uint(sacc[nf][2]);
            pw[(r_ + 8) * LDP + cb + 1] = __float_as_uint(sacc[nf][3]);
        }
        __syncwarp();

        // ---- O += P V ----
        #pragma unroll
        for (int kc = 0; kc < 8; kc++) {
            int kb = kc * 8;
            uint32_t af[4];
            af[0] = pw[r_ * LDP + kb + c_];
            af[1] = pw[(r_ + 8) * LDP + kb + c_];
            af[2] = pw[r_ * LDP + kb + c_ + 4];
            af[3] = pw[(r_ + 8) * LDP + kb + c_ + 4];
            #pragma unroll
            for (int nf = 0; nf < 8; nf++) {
                uint32_t b[2];
                b[0] = Vs[(kb + c_) * LDV + nf * 8 + r_];
                b[1] = Vs[(kb + c_ + 4) * LDV + nf * 8 + r_];
                mma8(o[nf], af, b);
            }
        }
        __syncwarp();
    }

    // ---- write ctx [B,S,E] ----
    int bb = bh >> 4, hh = bh & 15;
    float il0 = 1.f / l0, il1 = 1.f / l1;
    #pragma unroll
    for (int nf = 0; nf < 8; nf++) {
        int col = hh * 64 + nf * 8 + 2 * c_;
        *(float2*)&ctx[((size_t)bb * Sc + rr0) * Ec + col] =
            make_float2(rtf(o[nf][0] * il0), rtf(o[nf][1] * il0));
        *(float2*)&ctx[((size_t)bb * Sc + rr1) * Ec + col] =
            make_float2(rtf(o[nf][2] * il1), rtf(o[nf][3] * il1));
    }
}

// ---------------- launch ----------------
extern "C" void kernel_launch(void* const* d_in, const int* in_sizes, int n_in,
                              void* d_out, int out_size) {
    const float* x    = (const float*)d_in[0];
    const float* Wq   = (const float*)d_in[2];
    const float* bq   = (const float*)d_in[3];
    const float* Wk   = (const float*)d_in[4];
    const float* bk   = (const float*)d_in[5];
    const float* Wv   = (const float*)d_in[6];
    const float* bv   = (const float*)d_in[7];
    const float* Wo   = (const float*)d_in[8];
    const float* bo   = (const float*)d_in[9];
    const float* W1   = (const float*)d_in[10];
    const float* b1   = (const float*)d_in[11];
    const float* W2   = (const float*)d_in[12];
    const float* b2   = (const float*)d_in[13];
    const float* ln1g = (const float*)d_in[14];
    const float* ln1b = (const float*)d_in[15];
    const float* ln2g = (const float*)d_in[16];
    const float* ln2b = (const float*)d_in[17];
    float* out = (float*)d_out;

    float *n_, *q_, *k_, *v_, *ctx_, *res_, *x2_, *f1_, *wr_;
    cudaGetSymbolAddress((void**)&n_,   g_n);
    cudaGetSymbolAddress((void**)&q_,   g_q);
    cudaGetSymbolAddress((void**)&k_,   g_k);
    cudaGetSymbolAddress((void**)&v_,   g_v);
    cudaGetSymbolAddress((void**)&ctx_, g_ctx);
    cudaGetSymbolAddress((void**)&res_, g_res);
    cudaGetSymbolAddress((void**)&x2_,  g_x2);
    cudaGetSymbolAddress((void**)&f1_,  g_f1);
    cudaGetSymbolAddress((void**)&wr_,  g_wr);

    float* wq_ = wr_;
    float* wk_ = wr_ + 1*MB;
    float* wv_ = wr_ + 2*MB;
    float* wo_ = wr_ + 3*MB;
    float* w1_ = wr_ + 4*MB;
    float* w2_ = wr_ + 8*MB;

    cudaFuncSetAttribute(tgemm<EP_HEADS>, cudaFuncAttributeMaxDynamicSharedMemorySize, TG_SMEM);
    cudaFuncSetAttribute(tgemm<EP_RES>,   cudaFuncAttributeMaxDynamicSharedMemorySize, TG_SMEM);
    cudaFuncSetAttribute(tgemm<EP_GELU>,  cudaFuncAttributeMaxDynamicSharedMemorySize, TG_SMEM);
    cudaFuncSetAttribute(attn_tc, cudaFuncAttributeMaxDynamicSharedMemorySize, ATTN_SMEM);

    // 0. pre-round all weights (one launch; 3M float4)
    round_all<<<(12*MB/4)/256, 256>>>(Wq, Wk, Wv, Wo, W1, W2, wr_);

    // 1. LN1 (output tf32-rounded: feeds GEMMs only)
    ln_kernel<true><<<Mc, 256>>>(x, ln1g, ln1b, n_);

    // 2. Q/K/V projections -> [B,H,S,D] (outputs tf32-rounded)
    tgemm<EP_HEADS><<<dim3(Ec/BN, Mc/BM), 256, TG_SMEM>>>(n_, wq_, bq, nullptr, q_, Mc, Ec, Ec);
    tgemm<EP_HEADS><<<dim3(Ec/BN, Mc/BM), 256, TG_SMEM>>>(n_, wk_, bk, nullptr, k_, Mc, Ec, Ec);
    tgemm<EP_HEADS><<<dim3(Ec/BN, Mc/BM), 256, TG_SMEM>>>(n_, wv_, bv, nullptr, v_, Mc, Ec, Ec);

    // 3. Flash attention (tf32 TC, Q-tile 128) -> ctx [B,S,E]
    attn_tc<<<dim3(Sc/QT, Bc*Hc), 256, ATTN_SMEM>>>(q_, k_, v_, ctx_);

    // 4. Wo projection + residual with x (full fp32 residual)
    tgemm<EP_RES><<<dim3(Ec/BN, Mc/BM), 256, TG_SMEM>>>(ctx_, wo_, bo, x, res_, Mc, Ec, Ec);

    // 5. LN2 (NOT rounded: x2 is also the final residual)
    ln_kernel<false><<<Mc, 256>>>(res_, ln2g, ln2b, x2_);

    // 6. FFN1 + exact GELU (output rounded)
    tgemm<EP_GELU><<<dim3(Fc/BN, Mc/BM), 256, TG_SMEM>>>(x2_, w1_, b1, nullptr, f1_, Mc, Fc, Ec);

    // 7. FFN2 + bias + residual(x2) -> out
    tgemm<EP_RES><<<dim3(Ec/BN, Mc/BM), 256, TG_SMEM>>>(f1_, w2_, b2, x2_, out, Mc, Ec, Fc);
}

// round 7
// speedup vs baseline: 1.0252x; 1.0252x over previous
#include <cuda_runtime.h>
#include <math.h>
#include <stdint.h>

#define Bc 2
#define Sc 2048
#define Ec 1024
#define Hc 16
#define Dc 64
#define Fc 4096
#define Mc (Bc*Sc)          // 4096 rows
#define MB (1024*1024)

// ---------------- scratch (no cudaMalloc allowed) ----------------
__device__ float g_n  [Mc*Ec];
__device__ float g_q  [Mc*Ec];
__device__ float g_k  [Mc*Ec];
__device__ float g_v  [Mc*Ec];
__device__ float g_ctx[Mc*Ec];
__device__ float g_res[Mc*Ec];
__device__ float g_x2 [Mc*Ec];
__device__ float g_f1 [Mc*Fc];
__device__ float g_wr [12*MB];   // rounded weights: Wqkv concat [1024][3072] (3M), Wo (1M), W1 (4M), W2 (4M)
__device__ float g_bqkv[3072];   // concatenated rounded-path bias (bq|bk|bv)

// ---------------- helpers ----------------
__device__ __forceinline__ uint32_t f2tf(float f) {
    uint32_t u;
    asm("cvt.rna.tf32.f32 %0, %1;" : "=r"(u) : "f"(f));
    return u;
}
__device__ __forceinline__ float rtf(float f) { return __uint_as_float(f2tf(f)); }

__device__ __forceinline__ void mma8(float* c, const uint32_t* a, const uint32_t* b) {
    asm volatile(
        "mma.sync.aligned.m16n8k8.row.col.f32.tf32.tf32.f32 "
        "{%0,%1,%2,%3}, {%4,%5,%6,%7}, {%8,%9}, {%0,%1,%2,%3};\n"
        : "+f"(c[0]), "+f"(c[1]), "+f"(c[2]), "+f"(c[3])
        : "r"(a[0]), "r"(a[1]), "r"(a[2]), "r"(a[3]),
          "r"(b[0]), "r"(b[1]));
}

__device__ __forceinline__ void cp16(uint32_t dst, const float* src) {
    asm volatile("cp.async.cg.shared.global [%0], [%1], 16;" :: "r"(dst), "l"(src));
}
#define CP_COMMIT() asm volatile("cp.async.commit_group;")
#define CP_WAIT0()  asm volatile("cp.async.wait_group 0;")
#define CP_WAIT1()  asm volatile("cp.async.wait_group 1;")

// ---------------- fused rounding + concat: 4 float4 per thread (MLP=4) ----------------
// dst layout (floats): [0,3M) Wqkv concat rows k:[1024] x cols n:[3072];
// [3M,4M) Wo; [4M,8M) W1; [8M,12M) W2. Bias concat -> g_bqkv[3072].
#define RTOT (12*MB + 3072)

__global__ void __launch_bounds__(256) round_all(const float* __restrict__ Wq,
                                                 const float* __restrict__ Wk,
                                                 const float* __restrict__ Wv,
                                                 const float* __restrict__ Wo,
                                                 const float* __restrict__ W1,
                                                 const float* __restrict__ W2,
                                                 const float* __restrict__ bq,
                                                 const float* __restrict__ bk,
                                                 const float* __restrict__ bv,
                                                 float* __restrict__ dst,
                                                 float* __restrict__ bqkv) {
    long fi = ((long)blockIdx.x * 256 + threadIdx.x) * 16;   // 16 consecutive floats
    if (fi >= RTOT) return;
    const float* src;
    float* d;
    if (fi < 3*MB) {                       // Wqkv concat
        long k = fi / 3072, n = fi - k * 3072;
        int mat = (int)(n >> 10);
        long within = n & 1023;
        const float* W = (mat == 0) ? Wq : (mat == 1) ? Wk : Wv;
        src = W + k * 1024 + within;
        d = dst + fi;
    } else if (fi < 4*MB)  { src = Wo + (fi - 3*MB); d = dst + fi; }
    else if   (fi < 8*MB)  { src = W1 + (fi - 4*MB); d = dst + fi; }
    else if   (fi < 12*MB) { src = W2 + (fi - 8*MB); d = dst + fi; }
    else {                                 // bias concat
        long j = fi - 12*MB;
        int mat = (int)(j >> 10);
        src = ((mat == 0) ? bq : (mat == 1) ? bk : bv) + (j & 1023);
        d = bqkv + j;
    }
    float4 a = ((const float4*)src)[0];
    float4 b = ((const float4*)src)[1];
    float4 c = ((const float4*)src)[2];
    float4 e = ((const float4*)src)[3];
    a.x=rtf(a.x); a.y=rtf(a.y); a.z=rtf(a.z); a.w=rtf(a.w);
    b.x=rtf(b.x); b.y=rtf(b.y); b.z=rtf(b.z); b.w=rtf(b.w);
    c.x=rtf(c.x); c.y=rtf(c.y); c.z=rtf(c.z); c.w=rtf(c.w);
    e.x=rtf(e.x); e.y=rtf(e.y); e.z=rtf(e.z); e.w=rtf(e.w);
    ((float4*)d)[0]=a; ((float4*)d)[1]=b; ((float4*)d)[2]=c; ((float4*)d)[3]=e;
}

// ---------------- LayerNorm ----------------
template<bool RND>
__global__ void __launch_bounds__(256) ln_kernel(const float* __restrict__ x,
                                                 const float* __restrict__ g,
                                                 const float* __restrict__ b,
                                                 float* __restrict__ out) {
    int row = blockIdx.x;
    int tid = threadIdx.x;
    const float4* xr = (const float4*)(x + (size_t)row * Ec);
    float4 xv = xr[tid];
    float s  = xv.x + xv.y + xv.z + xv.w;
    float sq = xv.x*xv.x + xv.y*xv.y + xv.z*xv.z + xv.w*xv.w;
    #pragma unroll
    for (int o = 16; o; o >>= 1) {
        s  += __shfl_xor_sync(0xffffffffu, s,  o);
        sq += __shfl_xor_sync(0xffffffffu, sq, o);
    }
    __shared__ float ws[8], wq[8];
    __shared__ float s_mu, s_rstd;
    int lane = tid & 31, wid = tid >> 5;
    if (lane == 0) { ws[wid] = s; wq[wid] = sq; }
    __syncthreads();
    if (tid == 0) {
        float S = 0.f, Q = 0.f;
        #pragma unroll
        for (int i = 0; i < 8; i++) { S += ws[i]; Q += wq[i]; }
        float mu  = S * (1.0f / Ec);
        float var = Q * (1.0f / Ec) - mu * mu;
        s_mu = mu;
        s_rstd = rsqrtf(var + 1e-5f);
    }
    __syncthreads();
    float mu = s_mu, rstd = s_rstd;
    float4 gv = ((const float4*)g)[tid];
    float4 bv = ((const float4*)b)[tid];
    float4 ov;
    ov.x = (xv.x - mu) * rstd * gv.x + bv.x;
    ov.y = (xv.y - mu) * rstd * gv.y + bv.y;
    ov.z = (xv.z - mu) * rstd * gv.z + bv.z;
    ov.w = (xv.w - mu) * rstd * gv.w + bv.w;
    if (RND) { ov.x = rtf(ov.x); ov.y = rtf(ov.y); ov.z = rtf(ov.z); ov.w = rtf(ov.w); }
    ((float4*)(out + (size_t)row * Ec))[tid] = ov;
}

// ---------------- tf32 TC GEMM: 128x128x32, 8 warps, 3-stage cp.async ----------------
enum { EP_PLAIN = 0, EP_HEADS = 1, EP_RES = 2, EP_GELU = 3 };

#define BM 128
#define BN 128
#define BK 32
#define LDA 36      // bank = (4m + c) % 32 conflict-free
#define LDB 136     // bank = (8c + n) % 32 conflict-free
#define STG_A (BM * LDA)            // 4608 floats
#define STG_B (BK * LDB)            // 4352 floats
#define STG   (STG_A + STG_B)       // 8960 floats
#define NSTAGE 3
#define TG_SMEM (NSTAGE * STG * 4)  // 107520 bytes

template<int EP>
__global__ void __launch_bounds__(256, 2) tgemm(const float* __restrict__ A,
                                                const float* __restrict__ W,
                                                const float* __restrict__ bias,
                                                const float* __restrict__ res,
                                                float* __restrict__ C,
                                                float* __restrict__ C2,
                                                float* __restrict__ C3,
                                                int M, int N, int K) {
    extern __shared__ float sh[];
    uint32_t smem_u = (uint32_t)__cvta_generic_to_shared(sh);

    int tid  = threadIdx.x;
    int lane = tid & 31;
    int w    = tid >> 5;
    int wm   = (w & 3) * 32;
    int wn   = (w >> 2) * 64;
    int row0 = blockIdx.y * BM;
    int col0 = blockIdx.x * BN;

    const float* Ab = A + (size_t)row0 * K;
    const float* Wb = W + col0;

    int ar  = tid >> 3, akc = (tid & 7) * 4;   // + i*32 rows
    int bkr = tid >> 5, bnc = (tid & 31) * 4;  // + i*8 rows

    auto issue = [&](int k0, int s) {
        uint32_t sa = smem_u + (uint32_t)(s * STG) * 4u;
        uint32_t sb = sa + (uint32_t)STG_A * 4u;
        #pragma unroll
        for (int i = 0; i < 4; i++) {
            int r = ar + i * 32;
            cp16(sa + (uint32_t)(r * LDA + akc) * 4u, Ab + (size_t)r * K + k0 + akc);
            int kr = bkr + i * 8;
            cp16(sb + (uint32_t)(kr * LDB + bnc) * 4u, Wb + (size_t)(k0 + kr) * N + bnc);
        }
        CP_COMMIT();
    };

    float acc[2][8][4];
    #pragma unroll
    for (int mi = 0; mi < 2; mi++)
        #pragma unroll
        for (int ni = 0; ni < 8; ni++)
            #pragma unroll
            for (int q = 0; q < 4; q++) acc[mi][ni][q] = 0.f;

    int nk = K / BK;
    issue(0, 0);
    issue(BK, 1);

    int r_ = lane >> 2, c_ = lane & 3;
    int st = 0;
    for (int kt = 0; kt < nk; kt++) {
        if (kt + 1 < nk) { CP_WAIT1(); } else { CP_WAIT0(); }
        __syncthreads();
        if (kt + 2 < nk) {
            int s2 = st + 2; if (s2 >= NSTAGE) s2 -= NSTAGE;
            issue((kt + 2) * BK, s2);
        }

        const uint32_t* Sa = (const uint32_t*)(sh + st * STG);
        const uint32_t* Sb = Sa + STG_A;

        #pragma unroll
        for (int ks = 0; ks < 4; ks++) {
            int kb = ks * 8;
            uint32_t af[2][4], bf[8][2];
            #pragma unroll
            for (int mi = 0; mi < 2; mi++) {
                int m = wm + mi * 16 + r_;
                af[mi][0] = Sa[m * LDA + kb + c_];
                af[mi][1] = Sa[(m + 8) * LDA + kb + c_];
                af[mi][2] = Sa[m * LDA + kb + c_ + 4];
                af[mi][3] = Sa[(m + 8) * LDA + kb + c_ + 4];
            }
            #pragma unroll
            for (int ni = 0; ni < 8; ni++) {
                int n = wn + ni * 8 + r_;
                bf[ni][0] = Sb[(kb + c_) * LDB + n];
                bf[ni][1] = Sb[(kb + c_ + 4) * LDB + n];
            }
            #pragma unroll
            for (int mi = 0; mi < 2; mi++)
                #pragma unroll
                for (int ni = 0; ni < 8; ni++)
                    mma8(acc[mi][ni], af[mi], bf[ni]);
        }
        if (++st == NSTAGE) st = 0;
    }

    // ---- epilogue ----
    int c2 = (lane & 3) * 2;
    #pragma unroll
    for (int mi = 0; mi < 2; mi++) {
        #pragma unroll
        for (int ni = 0; ni < 8; ni++) {
            #pragma unroll
            for (int h = 0; h < 2; h++) {
                int row = row0 + wm + mi * 16 + r_ + h * 8;
                int col = col0 + wn + ni * 8 + c2;
                float v0 = acc[mi][ni][h * 2 + 0] + bias[col];
                float v1 = acc[mi][ni][h * 2 + 1] + bias[col + 1];
                if (EP == EP_GELU) {
                    v0 = 0.5f * v0 * (1.f + erff(v0 * 0.70710678118654752f));
                    v1 = 0.5f * v1 * (1.f + erff(v1 * 0.70710678118654752f));
                }
                if (EP == EP_RES) {
                    v0 += res[(size_t)row * N + col];
                    v1 += res[(size_t)row * N + col + 1];
                }
                if (EP == EP_HEADS || EP == EP_GELU) { v0 = rtf(v0); v1 = rtf(v1); }
                if (EP == EP_HEADS) {
                    int mat = col >> 10;           // 0=Q,1=K,2=V (N=3072)
                    int cc  = col & 1023;
                    int bb = row >> 11, ss = row & 2047;
                    int hh = cc >> 6,  dd = cc & 63;
                    float* dst = (mat == 0) ? C : (mat == 1) ? C2 : C3;
                    *(float2*)&dst[(((size_t)(bb * Hc + hh)) * Sc + ss) * Dc + dd] =
                        make_float2(v0, v1);
                } else {
                    *(float2*)&C[(size_t)row * N + col] = make_float2(v0, v1);
                }
            }
        }
    }
}

// ---------------- tf32 TC flash attention: 64x64 tiles, 128 thr, cp.async KV ----------------
#define LDK 68
#define LDV 72
#define LDP 68
#define KV_STG (64*LDK + 64*LDV)                 // floats per stage
#define ATTN_SMEM ((2*KV_STG + 64*LDP) * 4)      // 89088 bytes

__global__ void __launch_bounds__(128, 2) attn_tc(const float* __restrict__ Q,
                                                  const float* __restrict__ K,
                                                  const float* __restrict__ V,
                                                  float* __restrict__ ctx) {
    extern __shared__ uint32_t smu[];
    uint32_t smem_u = (uint32_t)__cvta_generic_to_shared(smu);
    uint32_t* Ps = smu + 2 * KV_STG;

    int tid = threadIdx.x, lane = tid & 31, w = tid >> 5;
    int r_ = lane >> 2, c_ = lane & 3;
    int qt = (int)gridDim.x - 1 - (int)blockIdx.x;
    int bh = blockIdx.y;
    int q0 = qt * 64;

    const float* Qb = Q + (size_t)bh * Sc * Dc;
    const float* Kb = K + (size_t)bh * Sc * Dc;
    const float* Vb = V + (size_t)bh * Sc * Dc;

    auto issue_kv = [&](int k0, int s) {
        uint32_t kb_ = smem_u + (uint32_t)(s * KV_STG) * 4u;
        uint32_t vb_ = kb_ + (uint32_t)(64 * LDK) * 4u;
        #pragma unroll
        for (int it = 0; it < 8; it++) {
            int idx = tid + it * 128;
            int r = idx >> 4, d4 = (idx & 15) * 4;
            cp16(kb_ + (uint32_t)(r * LDK + d4) * 4u, Kb + (size_t)(k0 + r) * Dc + d4);
            cp16(vb_ + (uint32_t)(r * LDV + d4) * 4u, Vb + (size_t)(k0 + r) * Dc + d4);
        }
        CP_COMMIT();
    };

    issue_kv(0, 0);

    // ---- stage Q (pre-scaled; q_ is tf32-rounded at producer, x0.125 exact) ----
    #pragma unroll
    for (int it = 0; it < 8; it++) {
        int idx = tid + it * 128;
        int r = idx >> 4, d4 = (idx & 15) * 4;
        float4 f = *(const float4*)(Qb + (size_t)(q0 + r) * Dc + d4);
        Ps[r * LDP + d4 + 0] = __float_as_uint(f.x * 0.125f);
        Ps[r * LDP + d4 + 1] = __float_as_uint(f.y * 0.125f);
        Ps[r * LDP + d4 + 2] = __float_as_uint(f.z * 0.125f);
        Ps[r * LDP + d4 + 3] = __float_as_uint(f.w * 0.125f);
    }
    __syncthreads();
    uint32_t qf[8][4];
    {
        const uint32_t* pw0 = Ps + w * 16 * LDP;
        #pragma unroll
        for (int kc = 0; kc < 8; kc++) {
            int kb = kc * 8;
            qf[kc][0] = pw0[r_ * LDP + kb + c_];
            qf[kc][1] = pw0[(r_ + 8) * LDP + kb + c_];
            qf[kc][2] = pw0[r_ * LDP + kb + c_ + 4];
            qf[kc][3] = pw0[(r_ + 8) * LDP + kb + c_ + 4];
        }
    }

    float o[8][4];
    #pragma unroll
    for (int nf = 0; nf < 8; nf++)
        #pragma unroll
        for (int q = 0; q < 4; q++) o[nf][q] = 0.f;
    float m0 = -1e30f, m1 = -1e30f, l0 = 0.f, l1 = 0.f;

    uint32_t* pw = Ps + w * 16 * LDP;

    for (int kt = 0; kt <= qt; kt++) {
        CP_WAIT0();
        __syncthreads();
        if (kt + 1 <= qt) issue_kv((kt + 1) * 64, (kt + 1) & 1);

        const uint32_t* Ks = smu + (kt & 1) * KV_STG;
        const uint32_t* Vs = Ks + 64 * LDK;

        float sacc[8][4];
        #pragma unroll
        for (int nf = 0; nf < 8; nf++)
            #pragma unroll
            for (int q = 0; q < 4; q++) sacc[nf][q] = 0.f;
        #pragma unroll
        for (int kc = 0; kc < 8; kc++) {
            int kb = kc * 8;
            #pragma unroll
            for (int nf = 0; nf < 8; nf++) {
                uint32_t b[2];
                b[0] = Ks[(nf * 8 + r_) * LDK + kb + c_];
                b[1] = Ks[(nf * 8 + r_) * LDK + kb + c_ + 4];
                mma8(sacc[nf], qf[kc], b);
            }
        }

        if (kt == qt) {
            int rr = w * 16 + r_;
            #pragma unroll
            for (int nf = 0; nf < 8; nf++) {
                int cb = nf * 8 + 2 * c_;
                if (cb     > rr)     sacc[nf][0] = -1e30f;
                if (cb + 1 > rr)     sacc[nf][1] = -1e30f;
                if (cb     > rr + 8) sacc[nf][2] = -1e30f;
                if (cb + 1 > rr + 8) sacc[nf][3] = -1e30f;
            }
        }

        float mx0 = -1e30f, mx1 = -1e30f;
        #pragma unroll
        for (int nf = 0; nf < 8; nf++) {
            mx0 = fmaxf(mx0, fmaxf(sacc[nf][0], sacc[nf][1]));
            mx1 = fmaxf(mx1, fmaxf(sacc[nf][2], sacc[nf][3]));
        }
        mx0 = fmaxf(mx0, __shfl_xor_sync(0xffffffffu, mx0, 1));
        mx0 = fmaxf(mx0, __shfl_xor_sync(0xffffffffu, mx0, 2));
        mx1 = fmaxf(mx1, __shfl_xor_sync(0xffffffffu, mx1, 1));
        mx1 = fmaxf(mx1, __shfl_xor_sync(0xffffffffu, mx1, 2));
        float mn0 = fmaxf(m0, mx0), mn1 = fmaxf(m1, mx1);
        float es0 = __expf(m0 - mn0), es1 = __expf(m1 - mn1);
        m0 = mn0; m1 = mn1;
        float ls0 = 0.f, ls1 = 0.f;
        #pragma unroll
        for (int nf = 0; nf < 8; nf++) {
            sacc[nf][0] = __expf(sacc[nf][0] - mn0);
            sacc[nf][1] = __expf(sacc[nf][1] - mn0);
            sacc[nf][2] = __expf(sacc[nf][2] - mn1);
            sacc[nf][3] = __expf(sacc[nf][3] - mn1);
            ls0 += sacc[nf][0] + sacc[nf][1];
            ls1 += sacc[nf][2] + sacc[nf][3];
        }
        ls0 += __shfl_xor_sync(0xffffffffu, ls0, 1);
        ls0 += __shfl_xor_sync(0xffffffffu, ls0, 2);
        ls1 += __shfl_xor_sync(0xffffffffu, ls1, 1);
        ls1 += __shfl_xor_sync(0xffffffffu, ls1, 2);
        l0 = l0 * es0 + ls0;
        l1 = l1 * es1 + ls1;
        #pragma unroll
        for (int nf = 0; nf < 8; nf++) {
            o[nf][0] *= es0; o[nf][1] *= es0;
            o[nf][2] *= es1; o[nf][3] *= es1;
        }

        #pragma unroll
        for (int nf = 0; nf < 8; nf++) {
            int cb = nf * 8 + 2 * c_;
            pw[r_ * LDP + cb]           = __float_as_uint(sacc[nf][0]);
            pw[r_ * LDP + cb + 1]       = __float_as_uint(sacc[nf][1]);
            pw[(r_ + 8) * LDP + cb]     = __float_as_uint(sacc[nf][2]);
            pw[(r_ + 8) * LDP + cb + 1] = __float_as_uint(sacc[nf][3]);
        }
        __syncwarp();

        #pragma unroll
        for (int kc = 0; kc < 8; kc++) {
            int kb = kc * 8;
            uint32_t af[4];
            af[0] = pw[r_ * LDP + kb + c_];
            af[1] = pw[(r_ + 8) * LDP + kb + c_];
            af[2] = pw[r_ * LDP + kb + c_ + 4];
            af[3] = pw[(r_ + 8) * LDP + kb + c_ + 4];
            #pragma unroll
            for (int nf = 0; nf < 8; nf++) {
                uint32_t b[2];
                b[0] = Vs[(kb + c_) * LDV + nf * 8 + r_];
                b[1] = Vs[(kb + c_ + 4) * LDV + nf * 8 + r_];
                mma8(o[nf], af, b);
            }
        }
        __syncwarp();
    }

    int bb = bh >> 4, hh = bh & 15;
    int row0 = q0 + w * 16 + r_;
    float il0 = 1.f / l0, il1 = 1.f / l1;
    #pragma unroll
    for (int nf = 0; nf < 8; nf++) {
        int col = hh * 64 + nf * 8 + 2 * c_;
        *(float2*)&ctx[((size_t)bb * Sc + row0) * Ec + col] =
            make_float2(rtf(o[nf][0] * il0), rtf(o[nf][1] * il0));
        *(float2*)&ctx[((size_t)bb * Sc + row0 + 8) * Ec + col] =
            make_float2(rtf(o[nf][2] * il1), rtf(o[nf][3] * il1));
    }
}

// ---------------- launch ----------------
extern "C" void kernel_launch(void* const* d_in, const int* in_sizes, int n_in,
                              void* d_out, int out_size) {
    const float* x    = (const float*)d_in[0];
    const float* Wq   = (const float*)d_in[2];
    const float* bq   = (const float*)d_in[3];
    const float* Wk   = (const float*)d_in[4];
    const float* bk   = (const float*)d_in[5];
    const float* Wv   = (const float*)d_in[6];
    const float* bv   = (const float*)d_in[7];
    const float* Wo   = (const float*)d_in[8];
    const float* bo   = (const float*)d_in[9];
    const float* W1   = (const float*)d_in[10];
    const float* b1   = (const float*)d_in[11];
    const float* W2   = (const float*)d_in[12];
    const float* b2   = (const float*)d_in[13];
    const float* ln1g = (const float*)d_in[14];
    const float* ln1b = (const float*)d_in[15];
    const float* ln2g = (const float*)d_in[16];
    const float* ln2b = (const float*)d_in[17];
    float* out = (float*)d_out;

    float *n_, *q_, *k_, *v_, *ctx_, *res_, *x2_, *f1_, *wr_, *bqkv_;
    cudaGetSymbolAddress((void**)&n_,   g_n);
    cudaGetSymbolAddress((void**)&q_,   g_q);
    cudaGetSymbolAddress((void**)&k_,   g_k);
    cudaGetSymbolAddress((void**)&v_,   g_v);
    cudaGetSymbolAddress((void**)&ctx_, g_ctx);
    cudaGetSymbolAddress((void**)&res_, g_res);
    cudaGetSymbolAddress((void**)&x2_,  g_x2);
    cudaGetSymbolAddress((void**)&f1_,  g_f1);
    cudaGetSymbolAddress((void**)&wr_,  g_wr);
    cudaGetSymbolAddress((void**)&bqkv_, g_bqkv);

    float* wqkv_ = wr_;            // 3M floats [1024][3072]
    float* wo_   = wr_ + 3*MB;
    float* w1_   = wr_ + 4*MB;
    float* w2_   = wr_ + 8*MB;

    cudaFuncSetAttribute(tgemm<EP_HEADS>, cudaFuncAttributeMaxDynamicSharedMemorySize, TG_SMEM);
    cudaFuncSetAttribute(tgemm<EP_RES>,   cudaFuncAttributeMaxDynamicSharedMemorySize, TG_SMEM);
    cudaFuncSetAttribute(tgemm<EP_GELU>,  cudaFuncAttributeMaxDynamicSharedMemorySize, TG_SMEM);
    cudaFuncSetAttribute(attn_tc, cudaFuncAttributeMaxDynamicSharedMemorySize, ATTN_SMEM);

    // 0. round + concat all weights/bias (one launch, MLP=4/thread)
    int rblocks = (RTOT / 16 + 255) / 256;
    round_all<<<rblocks, 256>>>(Wq, Wk, Wv, Wo, W1, W2, bq, bk, bv, wr_, bqkv_);

    // 1. LN1 (tf32-rounded output: feeds GEMM only)
    ln_kernel<true><<<Mc, 256>>>(x, ln1g, ln1b, n_);

    // 2. fused QKV projection (N=3072) -> q/k/v in [B,H,S,D], tf32-rounded
    tgemm<EP_HEADS><<<dim3(3072/BN, Mc/BM), 256, TG_SMEM>>>(n_, wqkv_, bqkv_, nullptr,
                                                            q_, k_, v_, Mc, 3072, Ec);

    // 3. flash attention (tf32 TC) -> ctx [B,S,E] (rounded)
    attn_tc<<<dim3(Sc/64, Bc*Hc), 128, ATTN_SMEM>>>(q_, k_, v_, ctx_);

    // 4. Wo projection + residual with x (full fp32 residual)
    tgemm<EP_RES><<<dim3(Ec/BN, Mc/BM), 256, TG_SMEM>>>(ctx_, wo_, bo, x,
                                                        res_, nullptr, nullptr, Mc, Ec, Ec);

    // 5. LN2 (NOT rounded: x2 is also the final residual)
    ln_kernel<false><<<Mc, 256>>>(res_, ln2g, ln2b, x2_);

    // 6. FFN1 + exact GELU (output rounded)
    tgemm<EP_GELU><<<dim3(Fc/BN, Mc/BM), 256, TG_SMEM>>>(x2_, w1_, b1, nullptr,
                                                         f1_, nullptr, nullptr, Mc, Fc, Ec);

    // 7. FFN2 + bias + residual(x2) -> out
    tgemm<EP_RES><<<dim3(Ec/BN, Mc/BM), 256, TG_SMEM>>>(f1_, w2_, b2, x2_,
                                                        out, nullptr, nullptr, Mc, Ec, Fc);
}

// round 8
// speedup vs baseline: 1.5251x; 1.4877x over previous
#include <cuda_runtime.h>
#include <cuda_fp16.h>
#include <math.h>
#include <stdint.h>

#define Bc 2
#define Sc 2048
#define Ec 1024
#define Hc 16
#define Dc 64
#define Fc 4096
#define Mc (Bc*Sc)          // 4096 rows
#define MB (1024*1024)

// ---------------- scratch (no cudaMalloc allowed) ----------------
__device__ __half g_n  [Mc*Ec];     // LN1 out (half, GEMM A)
__device__ float  g_q  [Mc*Ec];
__device__ float  g_k  [Mc*Ec];
__device__ float  g_v  [Mc*Ec];
__device__ __half g_ctx[Mc*Ec];     // attn out (half, GEMM A)
__device__ float  g_res[Mc*Ec];
__device__ float  g_x2 [Mc*Ec];     // LN2 out fp32 (residual)
__device__ __half g_x2h[Mc*Ec];     // LN2 out half (GEMM A)
__device__ __half g_f1 [Mc*Fc];     // GELU out (half, GEMM A)
__device__ uint32_t g_wp[6*MB];     // packed fp16 weights, k-interleaved half2 [K/2][N]
__device__ float  g_bqkv[3072];     // concat bias

// packed-weight word offsets
#define WP_QKV 0
#define WP_O   (3*MB/2)
#define WP_W1  (2*MB)
#define WP_W2  (4*MB)
#define WP_TOT (6*MB)

// ---------------- helpers ----------------
__device__ __forceinline__ uint32_t f2tf(float f) {
    uint32_t u;
    asm("cvt.rna.tf32.f32 %0, %1;" : "=r"(u) : "f"(f));
    return u;
}
__device__ __forceinline__ float rtf(float f) { return __uint_as_float(f2tf(f)); }

__device__ __forceinline__ uint32_t packh2(float lo, float hi) {
    __half2 h = __floats2half2_rn(lo, hi);
    return *(uint32_t*)&h;
}

// tf32 k8 (attention only)
__device__ __forceinline__ void mma8(float* c, const uint32_t* a, const uint32_t* b) {
    asm volatile(
        "mma.sync.aligned.m16n8k8.row.col.f32.tf32.tf32.f32 "
        "{%0,%1,%2,%3}, {%4,%5,%6,%7}, {%8,%9}, {%0,%1,%2,%3};\n"
        : "+f"(c[0]), "+f"(c[1]), "+f"(c[2]), "+f"(c[3])
        : "r"(a[0]), "r"(a[1]), "r"(a[2]), "r"(a[3]),
          "r"(b[0]), "r"(b[1]));
}

// fp16 k16 (GEMMs)
__device__ __forceinline__ void mma16(float* c, const uint32_t* a, const uint32_t* b) {
    asm volatile(
        "mma.sync.aligned.m16n8k16.row.col.f32.f16.f16.f32 "
        "{%0,%1,%2,%3}, {%4,%5,%6,%7}, {%8,%9}, {%0,%1,%2,%3};\n"
        : "+f"(c[0]), "+f"(c[1]), "+f"(c[2]), "+f"(c[3])
        : "r"(a[0]), "r"(a[1]), "r"(a[2]), "r"(a[3]),
          "r"(b[0]), "r"(b[1]));
}

__device__ __forceinline__ void cp16(uint32_t dst, const void* src) {
    asm volatile("cp.async.cg.shared.global [%0], [%1], 16;" :: "r"(dst), "l"(src));
}
#define CP_COMMIT() asm volatile("cp.async.commit_group;")
#define CP_WAIT0()  asm volatile("cp.async.wait_group 0;")
#define CP_WAIT1()  asm volatile("cp.async.wait_group 1;")

// ---------------- weight convert+pack: fp32 [K][N] -> half2 word [K/2][N] ----------------
__global__ void __launch_bounds__(256) convert_all(const float* __restrict__ Wq,
                                                   const float* __restrict__ Wk,
                                                   const float* __restrict__ Wv,
                                                   const float* __restrict__ Wo,
                                                   const float* __restrict__ W1,
                                                   const float* __restrict__ W2,
                                                   const float* __restrict__ bq,
                                                   const float* __restrict__ bk,
                                                   const float* __restrict__ bv,
                                                   uint32_t* __restrict__ wp,
                                                   float* __restrict__ bqkv) {
    long wi = ((long)blockIdx.x * 256 + threadIdx.x) * 4;   // 4 words along n
    if (wi < WP_TOT) {
        const float *r0;
        long rstride;
        if (wi < WP_O) {                       // Wqkv concat: [512][3072]
            long k2 = wi / 3072, n = wi % 3072;
            int mat = (int)(n >> 10);
            const float* W = (mat == 0) ? Wq : (mat == 1) ? Wk : Wv;
            r0 = W + (2 * k2) * 1024 + (n & 1023);
            rstride = 1024;
        } else if (wi < WP_W1) {               // Wo: [512][1024]
            long off = wi - WP_O;
            r0 = Wo + (2 * (off >> 10)) * 1024 + (off & 1023);
            rstride = 1024;
        } else if (wi < WP_W2) {               // W1: [512][4096]
            long off = wi - WP_W1;
            r0 = W1 + (2 * (off >> 12)) * 4096 + (off & 4095);
            rstride = 4096;
        } else {                               // W2: [2048][1024]
            long off = wi - WP_W2;
            r0 = W2 + (2 * (off >> 10)) * 1024 + (off & 1023);
            rstride = 1024;
        }
        float4 e = *(const float4*)r0;
        float4 o = *(const float4*)(r0 + rstride);
        uint4 w;
        w.x = packh2(e.x, o.x);
        w.y = packh2(e.y, o.y);
        w.z = packh2(e.z, o.z);
        w.w = packh2(e.w, o.w);
        *(uint4*)(wp + wi) = w;
    } else if (wi < WP_TOT + 3072) {           // bias concat (fp32 copy)
        long j = wi - WP_TOT;
        int mat = (int)(j >> 10);
        const float* B = (mat == 0) ? bq : (mat == 1) ? bk : bv;
        *(float4*)(bqkv + j) = *(const float4*)(B + (j & 1023));
    }
}

// ---------------- LayerNorm: optional fp32 / half outputs ----------------
template<bool WF, bool WH>
__global__ void __launch_bounds__(256) ln_kernel(const float* __restrict__ x,
                                                 const float* __restrict__ g,
                                                 const float* __restrict__ b,
                                                 float* __restrict__ out_f,
                                                 __half* __restrict__ out_h) {
    int row = blockIdx.x;
    int tid = threadIdx.x;
    const float4* xr = (const float4*)(x + (size_t)row * Ec);
    float4 xv = xr[tid];
    float s  = xv.x + xv.y + xv.z + xv.w;
    float sq = xv.x*xv.x + xv.y*xv.y + xv.z*xv.z + xv.w*xv.w;
    #pragma unroll
    for (int o = 16; o; o >>= 1) {
        s  += __shfl_xor_sync(0xffffffffu, s,  o);
        sq += __shfl_xor_sync(0xffffffffu, sq, o);
    }
    __shared__ float ws[8], wq[8];
    __shared__ float s_mu, s_rstd;
    int lane = tid & 31, wid = tid >> 5;
    if (lane == 0) { ws[wid] = s; wq[wid] = sq; }
    __syncthreads();
    if (tid == 0) {
        float S = 0.f, Q = 0.f;
        #pragma unroll
        for (int i = 0; i < 8; i++) { S += ws[i]; Q += wq[i]; }
        float mu  = S * (1.0f / Ec);
        float var = Q * (1.0f / Ec) - mu * mu;
        s_mu = mu;
        s_rstd = rsqrtf(var + 1e-5f);
    }
    __syncthreads();
    float mu = s_mu, rstd = s_rstd;
    float4 gv = ((const float4*)g)[tid];
    float4 bv = ((const float4*)b)[tid];
    float4 ov;
    ov.x = (xv.x - mu) * rstd * gv.x + bv.x;
    ov.y = (xv.y - mu) * rstd * gv.y + bv.y;
    ov.z = (xv.z - mu) * rstd * gv.z + bv.z;
    ov.w = (xv.w - mu) * rstd * gv.w + bv.w;
    if (WF) ((float4*)(out_f + (size_t)row * Ec))[tid] = ov;
    if (WH) {
        uint2 hw;
        hw.x = packh2(ov.x, ov.y);
        hw.y = packh2(ov.z, ov.w);
        *(uint2*)(out_h + (size_t)row * Ec + tid * 4) = hw;
    }
}

// ---------------- fp16 TC GEMM: 128x128x32, 8 warps, 3-stage cp.async ----------------
enum { EP_PLAIN = 0, EP_HEADS = 1, EP_RES = 2, EP_GELU = 3 };

#define BM 128
#define BN 128
#define BKH 32                       // k-tile in halves
#define LDA2 20                      // As row stride in half2 words (bank: 20r+c bijective)
#define LDB2 136                     // Bs row stride in words (bank: 8c+r bijective)
#define STG_A2 (BM * LDA2)           // 2560 words
#define STG_B2 (16 * LDB2)           // 2176 words
#define STG2   (STG_A2 + STG_B2)     // 4736 words
#define NSTAGE 3
#define TG_SMEM (NSTAGE * STG2 * 4)  // 56832 bytes

// A: __half [M][K]; Wp: packed half2 words [K/2][N] at given offset
template<int EP>
__global__ void __launch_bounds__(256, 2) hgemm(const __half* __restrict__ A,
                                                const uint32_t* __restrict__ Wp,
                                                const float* __restrict__ bias,
                                                const float* __restrict__ res,
                                                float* __restrict__ C,
                                                float* __restrict__ C2,
                                                float* __restrict__ C3,
                                                __half* __restrict__ Ch,
                                                int M, int N, int K) {
    extern __shared__ uint32_t sh[];
    uint32_t smem_u = (uint32_t)__cvta_generic_to_shared(sh);

    int tid  = threadIdx.x;
    int lane = tid & 31;
    int w    = tid >> 5;
    int wm   = (w & 3) * 32;
    int wn   = (w >> 2) * 64;
    int row0 = blockIdx.y * BM;
    int col0 = blockIdx.x * BN;

    const __half* Ab = A + (size_t)row0 * K;
    const uint32_t* Wb = Wp + col0;

    auto issue = [&](int kt, int s) {
        uint32_t sa = smem_u + (uint32_t)(s * STG2) * 4u;
        uint32_t sb = sa + (uint32_t)STG_A2 * 4u;
        int k0 = kt * BKH;          // halves
        int k2b = kt * 16;          // half2 rows in Wp
        #pragma unroll
        for (int j = 0; j < 2; j++) {
            int idx = tid + j * 256;
            int r  = idx >> 2, wo = (idx & 3) * 4;                  // A: 4 words = 8 halves
            cp16(sa + (uint32_t)(r * LDA2 + wo) * 4u, Ab + (size_t)r * K + k0 + wo * 2);
            int kr = idx >> 5, nw = (idx & 31) * 4;                 // B: 4 words
            cp16(sb + (uint32_t)(kr * LDB2 + nw) * 4u, Wb + (size_t)(k2b + kr) * N + nw);
        }
        CP_COMMIT();
    };

    float acc[2][8][4];
    #pragma unroll
    for (int mi = 0; mi < 2; mi++)
        #pragma unroll
        for (int ni = 0; ni < 8; ni++)
            #pragma unroll
            for (int q = 0; q < 4; q++) acc[mi][ni][q] = 0.f;

    int nk = K / BKH;
    issue(0, 0);
    issue(1, 1);

    int r_ = lane >> 2, c_ = lane & 3;
    int st = 0;
    for (int kt = 0; kt < nk; kt++) {
        if (kt + 1 < nk) { CP_WAIT1(); } else { CP_WAIT0(); }
        __syncthreads();
        if (kt + 2 < nk) {
            int s2 = st + 2; if (s2 >= NSTAGE) s2 -= NSTAGE;
            issue(kt + 2, s2);
        }

        const uint32_t* Sa = sh + st * STG2;
        const uint32_t* Sb = Sa + STG_A2;

        #pragma unroll
        for (int ks = 0; ks < 2; ks++) {
            int kb2 = ks * 8;
            uint32_t af[2][4], bf[8][2];
            #pragma unroll
            for (int mi = 0; mi < 2; mi++) {
                int m = wm + mi * 16 + r_;
                af[mi][0] = Sa[m * LDA2 + kb2 + c_];
                af[mi][1] = Sa[(m + 8) * LDA2 + kb2 + c_];
                af[mi][2] = Sa[m * LDA2 + kb2 + c_ + 4];
                af[mi][3] = Sa[(m + 8) * LDA2 + kb2 + c_ + 4];
            }
            #pragma unroll
            for (int ni = 0; ni < 8; ni++) {
                int n = wn + ni * 8 + r_;
                bf[ni][0] = Sb[(kb2 + c_) * LDB2 + n];
                bf[ni][1] = Sb[(kb2 + c_ + 4) * LDB2 + n];
            }
            #pragma unroll
            for (int mi = 0; mi < 2; mi++)
                #pragma unroll
                for (int ni = 0; ni < 8; ni++)
                    mma16(acc[mi][ni], af[mi], bf[ni]);
        }
        if (++st == NSTAGE) st = 0;
    }

    // ---- epilogue ----
    int c2 = (lane & 3) * 2;
    #pragma unroll
    for (int mi = 0; mi < 2; mi++) {
        #pragma unroll
        for (int ni = 0; ni < 8; ni++) {
            #pragma unroll
            for (int h = 0; h < 2; h++) {
                int row = row0 + wm + mi * 16 + r_ + h * 8;
                int col = col0 + wn + ni * 8 + c2;
                float v0 = acc[mi][ni][h * 2 + 0] + bias[col];
                float v1 = acc[mi][ni][h * 2 + 1] + bias[col + 1];
                if (EP == EP_GELU) {
                    v0 = 0.5f * v0 * (1.f + erff(v0 * 0.70710678118654752f));
                    v1 = 0.5f * v1 * (1.f + erff(v1 * 0.70710678118654752f));
                    *(uint32_t*)&Ch[(size_t)row * N + col] = packh2(v0, v1);
                } else if (EP == EP_RES) {
                    v0 += res[(size_t)row * N + col];
                    v1 += res[(size_t)row * N + col + 1];
                    *(float2*)&C[(size_t)row * N + col] = make_float2(v0, v1);
                } else if (EP == EP_HEADS) {
                    v0 = rtf(v0); v1 = rtf(v1);    // attention smem path truncates; keep exact
                    int mat = col >> 10;           // 0=Q,1=K,2=V (N=3072)
                    int cc  = col & 1023;
                    int bb = row >> 11, ss = row & 2047;
                    int hh = cc >> 6,  dd = cc & 63;
                    float* dst = (mat == 0) ? C : (mat == 1) ? C2 : C3;
                    *(float2*)&dst[(((size_t)(bb * Hc + hh)) * Sc + ss) * Dc + dd] =
                        make_float2(v0, v1);
                }
            }
        }
    }
}

// ---------------- tf32 TC flash attention: 64x64 tiles, 128 thr, cp.async KV ----------------
#define LDK 68
#define LDV 72
#define LDP 68
#define KV_STG (64*LDK + 64*LDV)                 // floats per stage
#define ATTN_SMEM ((2*KV_STG + 64*LDP) * 4)      // 89088 bytes

__global__ void __launch_bounds__(128, 2) attn_tc(const float* __restrict__ Q,
                                                  const float* __restrict__ K,
                                                  const float* __restrict__ V,
                                                  __half* __restrict__ ctx) {
    extern __shared__ uint32_t smu[];
    uint32_t smem_u = (uint32_t)__cvta_generic_to_shared(smu);
    uint32_t* Ps = smu + 2 * KV_STG;

    int tid = threadIdx.x, lane = tid & 31, w = tid >> 5;
    int r_ = lane >> 2, c_ = lane & 3;
    int qt = (int)gridDim.x - 1 - (int)blockIdx.x;
    int bh = blockIdx.y;
    int q0 = qt * 64;

    const float* Qb = Q + (size_t)bh * Sc * Dc;
    const float* Kb = K + (size_t)bh * Sc * Dc;
    const float* Vb = V + (size_t)bh * Sc * Dc;

    auto issue_kv = [&](int k0, int s) {
        uint32_t kb_ = smem_u + (uint32_t)(s * KV_STG) * 4u;
        uint32_t vb_ = kb_ + (uint32_t)(64 * LDK) * 4u;
        #pragma unroll
        for (int it = 0; it < 8; it++) {
            int idx = tid + it * 128;
            int r = idx >> 4, d4 = (idx & 15) * 4;
            cp16(kb_ + (uint32_t)(r * LDK + d4) * 4u, Kb + (size_t)(k0 + r) * Dc + d4);
            cp16(vb_ + (uint32_t)(r * LDV + d4) * 4u, Vb + (size_t)(k0 + r) * Dc + d4);
        }
        CP_COMMIT();
    };

    issue_kv(0, 0);

    #pragma unroll
    for (int it = 0; it < 8; it++) {
        int idx = tid + it * 128;
        int r = idx >> 4, d4 = (idx & 15) * 4;
        float4 f = *(const float4*)(Qb + (size_t)(q0 + r) * Dc + d4);
        Ps[r * LDP + d4 + 0] = __float_as_uint(f.x * 0.125f);
        Ps[r * LDP + d4 + 1] = __float_as_uint(f.y * 0.125f);
        Ps[r * LDP + d4 + 2] = __float_as_uint(f.z * 0.125f);
        Ps[r * LDP + d4 + 3] = __float_as_uint(f.w * 0.125f);
    }
    __syncthreads();
    uint32_t qf[8][4];
    {
        const uint32_t* pw0 = Ps + w * 16 * LDP;
        #pragma unroll
        for (int kc = 0; kc < 8; kc++) {
            int kb = kc * 8;
            qf[kc][0] = pw0[r_ * LDP + kb + c_];
            qf[kc][1] = pw0[(r_ + 8) * LDP + kb + c_];
            qf[kc][2] = pw0[r_ * LDP + kb + c_ + 4];
            qf[kc][3] = pw0[(r_ + 8) * LDP + kb + c_ + 4];
        }
    }

    float o[8][4];
    #pragma unroll
    for (int nf = 0; nf < 8; nf++)
        #pragma unroll
        for (int q = 0; q < 4; q++) o[nf][q] = 0.f;
    float m0 = -1e30f, m1 = -1e30f, l0 = 0.f, l1 = 0.f;

    uint32_t* pw = Ps + w * 16 * LDP;

    for (int kt = 0; kt <= qt; kt++) {
        CP_WAIT0();
        __syncthreads();
        if (kt + 1 <= qt) issue_kv((kt + 1) * 64, (kt + 1) & 1);

        const uint32_t* Ks = smu + (kt & 1) * KV_STG;
        const uint32_t* Vs = Ks + 64 * LDK;

        float sacc[8][4];
        #pragma unroll
        for (int nf = 0; nf < 8; nf++)
            #pragma unroll
            for (int q = 0; q < 4; q++) sacc[nf][q] = 0.f;
        #pragma unroll
        for (int kc = 0; kc < 8; kc++) {
            int kb = kc * 8;
            #pragma unroll
            for (int nf = 0; nf < 8; nf++) {
                uint32_t b[2];
                b[0] = Ks[(nf * 8 + r_) * LDK + kb + c_];
                b[1] = Ks[(nf * 8 + r_) * LDK + kb + c_ + 4];
                mma8(sacc[nf], qf[kc], b);
            }
        }

        if (kt == qt) {
            int rr = w * 16 + r_;
            #pragma unroll
            for (int nf = 0; nf < 8; nf++) {
                int cb = nf * 8 + 2 * c_;
                if (cb     > rr)     sacc[nf][0] = -1e30f;
                if (cb + 1 > rr)     sacc[nf][1] = -1e30f;
                if (cb     > rr + 8) sacc[nf][2] = -1e30f;
                if (cb + 1 > rr + 8) sacc[nf][3] = -1e30f;
            }
        }

        float mx0 = -1e30f, mx1 = -1e30f;
        #pragma unroll
        for (int nf = 0; nf < 8; nf++) {
            mx0 = fmaxf(mx0, fmaxf(sacc[nf][0], sacc[nf][1]));
            mx1 = fmaxf(mx1, fmaxf(sacc[nf][2], sacc[nf][3]));
        }
        mx0 = fmaxf(mx0, __shfl_xor_sync(0xffffffffu, mx0, 1));
        mx0 = fmaxf(mx0, __shfl_xor_sync(0xffffffffu, mx0, 2));
        mx1 = fmaxf(mx1, __shfl_xor_sync(0xffffffffu, mx1, 1));
        mx1 = fmaxf(mx1, __shfl_xor_sync(0xffffffffu, mx1, 2));
        float mn0 = fmaxf(m0, mx0), mn1 = fmaxf(m1, mx1);
        float es0 = __expf(m0 - mn0), es1 = __expf(m1 - mn1);
        m0 = mn0; m1 = mn1;
        float ls0 = 0.f, ls1 = 0.f;
        #pragma unroll
        for (int nf = 0; nf < 8; nf++) {
            sacc[nf][0] = __expf(sacc[nf][0] - mn0);
            sacc[nf][1] = __expf(sacc[nf][1] - mn0);
            sacc[nf][2] = __expf(sacc[nf][2] - mn1);
            sacc[nf][3] = __expf(sacc[nf][3] - mn1);
            ls0 += sacc[nf][0] + sacc[nf][1];
            ls1 += sacc[nf][2] + sacc[nf][3];
        }
        ls0 += __shfl_xor_sync(0xffffffffu, ls0, 1);
        ls0 += __shfl_xor_sync(0xffffffffu, ls0, 2);
        ls1 += __shfl_xor_sync(0xffffffffu, ls1, 1);
        ls1 += __shfl_xor_sync(0xffffffffu, ls1, 2);
        l0 = l0 * es0 + ls0;
        l1 = l1 * es1 + ls1;
        #pragma unroll
        for (int nf = 0; nf < 8; nf++) {
            o[nf][0] *= es0; o[nf][1] *= es0;
            o[nf][2] *= es1; o[nf][3] *= es1;
        }

        #pragma unroll
        for (int nf = 0; nf < 8; nf++) {
            int cb = nf * 8 + 2 * c_;
            pw[r_ * LDP + cb]           = __float_as_uint(sacc[nf][0]);
            pw[r_ * LDP + cb + 1]       = __float_as_uint(sacc[nf][1]);
            pw[(r_ + 8) * LDP + cb]     = __float_as_uint(sacc[nf][2]);
            pw[(r_ + 8) * LDP + cb + 1] = __float_as_uint(sacc[nf][3]);
        }
        __syncwarp();

        #pragma unroll
        for (int kc = 0; kc < 8; kc++) {
            int kb = kc * 8;
            uint32_t af[4];
            af[0] = pw[r_ * LDP + kb + c_];
            af[1] = pw[(r_ + 8) * LDP + kb + c_];
            af[2] = pw[r_ * LDP + kb + c_ + 4];
            af[3] = pw[(r_ + 8) * LDP + kb + c_ + 4];
            #pragma unroll
            for (int nf = 0; nf < 8; nf++) {
                uint32_t b[2];
                b[0] = Vs[(kb + c_) * LDV + nf * 8 + r_];
                b[1] = Vs[(kb + c_ + 4) * LDV + nf * 8 + r_];
                mma8(o[nf], af, b);
            }
        }
        __syncwarp();
    }

    // ---- write ctx [B,S,E] as half ----
    int bb = bh >> 4, hh = bh & 15;
    int row0 = q0 + w * 16 + r_;
    float il0 = 1.f / l0, il1 = 1.f / l1;
    #pragma unroll
    for (int nf = 0; nf < 8; nf++) {
        int col = hh * 64 + nf * 8 + 2 * c_;
        *(uint32_t*)&ctx[((size_t)bb * Sc + row0) * Ec + col] =
            packh2(o[nf][0] * il0, o[nf][1] * il0);
        *(uint32_t*)&ctx[((size_t)bb * Sc + row0 + 8) * Ec + col] =
            packh2(o[nf][2] * il1, o[nf][3] * il1);
    }
}

// ---------------- launch ----------------
extern "C" void kernel_launch(void* const* d_in, const int* in_sizes, int n_in,
                              void* d_out, int out_size) {
    const float* x    = (const float*)d_in[0];
    const float* Wq   = (const float*)d_in[2];
    const float* bq   = (const float*)d_in[3];
    const float* Wk   = (const float*)d_in[4];
    const float* bk   = (const float*)d_in[5];
    const float* Wv   = (const float*)d_in[6];
    const float* bv   = (const float*)d_in[7];
    const float* Wo   = (const float*)d_in[8];
    const float* bo   = (const float*)d_in[9];
    const float* W1   = (const float*)d_in[10];
    const float* b1   = (const float*)d_in[11];
    const float* W2   = (const float*)d_in[12];
    const float* b2   = (const float*)d_in[13];
    const float* ln1g = (const float*)d_in[14];
    const float* ln1b = (const float*)d_in[15];
    const float* ln2g = (const float*)d_in[16];
    const float* ln2b = (const float*)d_in[17];
    float* out = (float*)d_out;

    __half *n_, *ctx_, *x2h_, *f1_;
    float *q_, *k_, *v_, *res_, *x2_, *bqkv_;
    uint32_t* wp_;
    cudaGetSymbolAddress((void**)&n_,   g_n);
    cudaGetSymbolAddress((void**)&q_,   g_q);
    cudaGetSymbolAddress((void**)&k_,   g_k);
    cudaGetSymbolAddress((void**)&v_,   g_v);
    cudaGetSymbolAddress((void**)&ctx_, g_ctx);
    cudaGetSymbolAddress((void**)&res_, g_res);
    cudaGetSymbolAddress((void**)&x2_,  g_x2);
    cudaGetSymbolAddress((void**)&x2h_, g_x2h);
    cudaGetSymbolAddress((void**)&f1_,  g_f1);
    cudaGetSymbolAddress((void**)&wp_,  g_wp);
    cudaGetSymbolAddress((void**)&bqkv_, g_bqkv);

    cudaFuncSetAttribute(hgemm<EP_HEADS>, cudaFuncAttributeMaxDynamicSharedMemorySize, TG_SMEM);
    cudaFuncSetAttribute(hgemm<EP_RES>,   cudaFuncAttributeMaxDynamicSharedMemorySize, TG_SMEM);
    cudaFuncSetAttribute(hgemm<EP_GELU>,  cudaFuncAttributeMaxDynamicSharedMemorySize, TG_SMEM);
    cudaFuncSetAttribute(attn_tc, cudaFuncAttributeMaxDynamicSharedMemorySize, ATTN_SMEM);

    // 0. convert + pack all weights to fp16 k-interleaved layout (one launch)
    long cblocks = ((WP_TOT + 3072) / 4 + 255) / 256;
    convert_all<<<(int)cblocks, 256>>>(Wq, Wk, Wv, Wo, W1, W2, bq, bk, bv, wp_, bqkv_);

    // 1. LN1 -> half (GEMM A only)
    ln_kernel<false, true><<<Mc, 256>>>(x, ln1g, ln1b, nullptr, n_);

    // 2. fused QKV projection (N=3072) -> q/k/v fp32 [B,H,S,D] (tf32-rounded for attn)
    hgemm<EP_HEADS><<<dim3(3072/BN, Mc/BM), 256, TG_SMEM>>>(n_, wp_ + WP_QKV, bqkv_, nullptr,
                                                            q_, k_, v_, nullptr, Mc, 3072, Ec);

    // 3. flash attention (tf32 TC) -> ctx half [B,S,E]
    attn_tc<<<dim3(Sc/64, Bc*Hc), 128, ATTN_SMEM>>>(q_, k_, v_, ctx_);

    // 4. Wo projection + residual with x -> res fp32
    hgemm<EP_RES><<<dim3(Ec/BN, Mc/BM), 256, TG_SMEM>>>(ctx_, wp_ + WP_O, bo, x,
                                                        res_, nullptr, nullptr, nullptr, Mc, Ec, Ec);

    // 5. LN2 -> x2 fp32 (residual) + x2h half (GEMM A)
    ln_kernel<true, true><<<Mc, 256>>>(res_, ln2g, ln2b, x2_, x2h_);

    // 6. FFN1 + exact GELU -> f1 half
    hgemm<EP_GELU><<<dim3(Fc/BN, Mc/BM), 256, TG_SMEM>>>(x2h_, wp_ + WP_W1, b1, nullptr,
                                                         nullptr, nullptr, nullptr, f1_, Mc, Fc, Ec);

    // 7. FFN2 + bias + residual(x2) -> out fp32
    hgemm<EP_RES><<<dim3(Ec/BN, Mc/BM), 256, TG_SMEM>>>(f1_, wp_ + WP_W2, b2, x2_,
                                                        out, nullptr, nullptr, nullptr, Mc, Ec, Fc);
}

// round 9
// speedup vs baseline: 1.7144x; 1.1241x over previous
#include <cuda_runtime.h>
#include <cuda_fp16.h>
#include <math.h>
#include <stdint.h>

#define Bc 2
#define Sc 2048
#define Ec 1024
#define Hc 16
#define Dc 64
#define Fc 4096
#define Mc (Bc*Sc)          // 4096 rows
#define MB (1024*1024)

// ---------------- scratch (no cudaMalloc allowed) ----------------
__device__ __half g_n  [Mc*Ec];     // LN1 out (half, GEMM A)
__device__ __half g_q  [Mc*Ec];     // Q half [B,H,S,D], pre-scaled by 0.125
__device__ __half g_k  [Mc*Ec];     // K half [B,H,S,D]
__device__ __half g_v  [Mc*Ec];     // V half [B,H,D,S]  (TRANSPOSED)
__device__ __half g_ctx[Mc*Ec];     // attn out (half, GEMM A)
__device__ float  g_res[Mc*Ec];
__device__ float  g_x2 [Mc*Ec];     // LN2 out fp32 (residual)
__device__ __half g_x2h[Mc*Ec];     // LN2 out half (GEMM A)
__device__ __half g_f1 [Mc*Fc];     // GELU out (half, GEMM A)
__device__ uint32_t g_wp[6*MB];     // packed fp16 weights, k-interleaved half2 [K/2][N]
__device__ float  g_bqkv[3072];     // concat bias

// packed-weight word offsets
#define WP_QKV 0
#define WP_O   (3*MB/2)
#define WP_W1  (2*MB)
#define WP_W2  (4*MB)
#define WP_TOT (6*MB)

// ---------------- helpers ----------------
__device__ __forceinline__ uint32_t packh2(float lo, float hi) {
    __half2 h = __floats2half2_rn(lo, hi);
    return *(uint32_t*)&h;
}

// fp16 k16 MMA
__device__ __forceinline__ void mma16(float* c, const uint32_t* a, const uint32_t* b) {
    asm volatile(
        "mma.sync.aligned.m16n8k16.row.col.f32.f16.f16.f32 "
        "{%0,%1,%2,%3}, {%4,%5,%6,%7}, {%8,%9}, {%0,%1,%2,%3};\n"
        : "+f"(c[0]), "+f"(c[1]), "+f"(c[2]), "+f"(c[3])
        : "r"(a[0]), "r"(a[1]), "r"(a[2]), "r"(a[3]),
          "r"(b[0]), "r"(b[1]));
}

__device__ __forceinline__ void cp16(uint32_t dst, const void* src) {
    asm volatile("cp.async.cg.shared.global [%0], [%1], 16;" :: "r"(dst), "l"(src));
}
#define CP_COMMIT() asm volatile("cp.async.commit_group;")
#define CP_WAIT0()  asm volatile("cp.async.wait_group 0;")
#define CP_WAIT1()  asm volatile("cp.async.wait_group 1;")

// ---------------- weight convert+pack: fp32 [K][N] -> half2 word [K/2][N] ----------------
__global__ void __launch_bounds__(256) convert_all(const float* __restrict__ Wq,
                                                   const float* __restrict__ Wk,
                                                   const float* __restrict__ Wv,
                                                   const float* __restrict__ Wo,
                                                   const float* __restrict__ W1,
                                                   const float* __restrict__ W2,
                                                   const float* __restrict__ bq,
                                                   const float* __restrict__ bk,
                                                   const float* __restrict__ bv,
                                                   uint32_t* __restrict__ wp,
                                                   float* __restrict__ bqkv) {
    long wi = ((long)blockIdx.x * 256 + threadIdx.x) * 4;   // 4 words along n
    if (wi < WP_TOT) {
        const float *r0;
        long rstride;
        if (wi < WP_O) {                       // Wqkv concat: [512][3072]
            long k2 = wi / 3072, n = wi % 3072;
            int mat = (int)(n >> 10);
            const float* W = (mat == 0) ? Wq : (mat == 1) ? Wk : Wv;
            r0 = W + (2 * k2) * 1024 + (n & 1023);
            rstride = 1024;
        } else if (wi < WP_W1) {               // Wo: [512][1024]
            long off = wi - WP_O;
            r0 = Wo + (2 * (off >> 10)) * 1024 + (off & 1023);
            rstride = 1024;
        } else if (wi < WP_W2) {               // W1: [512][4096]
            long off = wi - WP_W1;
            r0 = W1 + (2 * (off >> 12)) * 4096 + (off & 4095);
            rstride = 4096;
        } else {                               // W2: [2048][1024]
            long off = wi - WP_W2;
            r0 = W2 + (2 * (off >> 10)) * 1024 + (off & 1023);
            rstride = 1024;
        }
        float4 e = *(const float4*)r0;
        float4 o = *(const float4*)(r0 + rstride);
        uint4 w;
        w.x = packh2(e.x, o.x);
        w.y = packh2(e.y, o.y);
        w.z = packh2(e.z, o.z);
        w.w = packh2(e.w, o.w);
        *(uint4*)(wp + wi) = w;
    } else if (wi < WP_TOT + 3072) {           // bias concat (fp32 copy)
        long j = wi - WP_TOT;
        int mat = (int)(j >> 10);
        const float* B = (mat == 0) ? bq : (mat == 1) ? bk : bv;
        *(float4*)(bqkv + j) = *(const float4*)(B + (j & 1023));
    }
}

// ---------------- LayerNorm: optional fp32 / half outputs ----------------
template<bool WF, bool WH>
__global__ void __launch_bounds__(256) ln_kernel(const float* __restrict__ x,
                                                 const float* __restrict__ g,
                                                 const float* __restrict__ b,
                                                 float* __restrict__ out_f,
                                                 __half* __restrict__ out_h) {
    int row = blockIdx.x;
    int tid = threadIdx.x;
    const float4* xr = (const float4*)(x + (size_t)row * Ec);
    float4 xv = xr[tid];
    float s  = xv.x + xv.y + xv.z + xv.w;
    float sq = xv.x*xv.x + xv.y*xv.y + xv.z*xv.z + xv.w*xv.w;
    #pragma unroll
    for (int o = 16; o; o >>= 1) {
        s  += __shfl_xor_sync(0xffffffffu, s,  o);
        sq += __shfl_xor_sync(0xffffffffu, sq, o);
    }
    __shared__ float ws[8], wq[8];
    __shared__ float s_mu, s_rstd;
    int lane = tid & 31, wid = tid >> 5;
    if (lane == 0) { ws[wid] = s; wq[wid] = sq; }
    __syncthreads();
    if (tid == 0) {
        float S = 0.f, Q = 0.f;
        #pragma unroll
        for (int i = 0; i < 8; i++) { S += ws[i]; Q += wq[i]; }
        float mu  = S * (1.0f / Ec);
        float var = Q * (1.0f / Ec) - mu * mu;
        s_mu = mu;
        s_rstd = rsqrtf(var + 1e-5f);
    }
    __syncthreads();
    float mu = s_mu, rstd = s_rstd;
    float4 gv = ((const float4*)g)[tid];
    float4 bv = ((const float4*)b)[tid];
    float4 ov;
    ov.x = (xv.x - mu) * rstd * gv.x + bv.x;
    ov.y = (xv.y - mu) * rstd * gv.y + bv.y;
    ov.z = (xv.z - mu) * rstd * gv.z + bv.z;
    ov.w = (xv.w - mu) * rstd * gv.w + bv.w;
    if (WF) ((float4*)(out_f + (size_t)row * Ec))[tid] = ov;
    if (WH) {
        uint2 hw;
        hw.x = packh2(ov.x, ov.y);
        hw.y = packh2(ov.z, ov.w);
        *(uint2*)(out_h + (size_t)row * Ec + tid * 4) = hw;
    }
}

// ---------------- fp16 TC GEMM: 128x128x32, 8 warps, 3-stage cp.async ----------------
enum { EP_PLAIN = 0, EP_HEADS = 1, EP_RES = 2, EP_GELU = 3 };

#define BM 128
#define BN 128
#define BKH 32                       // k-tile in halves
#define LDA2 20                      // As row stride in half2 words
#define LDB2 136                     // Bs row stride in words
#define STG_A2 (BM * LDA2)           // 2560 words
#define STG_B2 (16 * LDB2)           // 2176 words
#define STG2   (STG_A2 + STG_B2)     // 4736 words
#define NSTAGE 3
#define TG_SMEM (NSTAGE * STG2 * 4)  // 56832 bytes

template<int EP>
__global__ void __launch_bounds__(256, 2) hgemm(const __half* __restrict__ A,
                                                const uint32_t* __restrict__ Wp,
                                                const float* __restrict__ bias,
                                                const float* __restrict__ res,
                                                float* __restrict__ C,
                                                __half* __restrict__ Ch,
                                                __half* __restrict__ Hq,
                                                __half* __restrict__ Hk,
                                                __half* __restrict__ Hv,
                                                int M, int N, int K) {
    extern __shared__ uint32_t sh[];
    uint32_t smem_u = (uint32_t)__cvta_generic_to_shared(sh);

    int tid  = threadIdx.x;
    int lane = tid & 31;
    int w    = tid >> 5;
    int wm   = (w & 3) * 32;
    int wn   = (w >> 2) * 64;
    int row0 = blockIdx.y * BM;
    int col0 = blockIdx.x * BN;

    const __half* Ab = A + (size_t)row0 * K;
    const uint32_t* Wb = Wp + col0;

    auto issue = [&](int kt, int s) {
        uint32_t sa = smem_u + (uint32_t)(s * STG2) * 4u;
        uint32_t sb = sa + (uint32_t)STG_A2 * 4u;
        int k0 = kt * BKH;          // halves
        int k2b = kt * 16;          // half2 rows in Wp
        #pragma unroll
        for (int j = 0; j < 2; j++) {
            int idx = tid + j * 256;
            int r  = idx >> 2, wo = (idx & 3) * 4;
            cp16(sa + (uint32_t)(r * LDA2 + wo) * 4u, Ab + (size_t)r * K + k0 + wo * 2);
            int kr = idx >> 5, nw = (idx & 31) * 4;
            cp16(sb + (uint32_t)(kr * LDB2 + nw) * 4u, Wb + (size_t)(k2b + kr) * N + nw);
        }
        CP_COMMIT();
    };

    float acc[2][8][4];
    #pragma unroll
    for (int mi = 0; mi < 2; mi++)
        #pragma unroll
        for (int ni = 0; ni < 8; ni++)
            #pragma unroll
            for (int q = 0; q < 4; q++) acc[mi][ni][q] = 0.f;

    int nk = K / BKH;
    issue(0, 0);
    issue(1, 1);

    int r_ = lane >> 2, c_ = lane & 3;
    int st = 0;
    for (int kt = 0; kt < nk; kt++) {
        if (kt + 1 < nk) { CP_WAIT1(); } else { CP_WAIT0(); }
        __syncthreads();
        if (kt + 2 < nk) {
            int s2 = st + 2; if (s2 >= NSTAGE) s2 -= NSTAGE;
            issue(kt + 2, s2);
        }

        const uint32_t* Sa = sh + st * STG2;
        const uint32_t* Sb = Sa + STG_A2;

        #pragma unroll
        for (int ks = 0; ks < 2; ks++) {
            int kb2 = ks * 8;
            uint32_t af[2][4], bf[8][2];
            #pragma unroll
            for (int mi = 0; mi < 2; mi++) {
                int m = wm + mi * 16 + r_;
                af[mi][0] = Sa[m * LDA2 + kb2 + c_];
                af[mi][1] = Sa[(m + 8) * LDA2 + kb2 + c_];
                af[mi][2] = Sa[m * LDA2 + kb2 + c_ + 4];
                af[mi][3] = Sa[(m + 8) * LDA2 + kb2 + c_ + 4];
            }
            #pragma unroll
            for (int ni = 0; ni < 8; ni++) {
                int n = wn + ni * 8 + r_;
                bf[ni][0] = Sb[(kb2 + c_) * LDB2 + n];
                bf[ni][1] = Sb[(kb2 + c_ + 4) * LDB2 + n];
            }
            #pragma unroll
            for (int mi = 0; mi < 2; mi++)
                #pragma unroll
                for (int ni = 0; ni < 8; ni++)
                    mma16(acc[mi][ni], af[mi], bf[ni]);
        }
        if (++st == NSTAGE) st = 0;
    }

    // ---- epilogue ----
    int c2 = (lane & 3) * 2;
    #pragma unroll
    for (int mi = 0; mi < 2; mi++) {
        #pragma unroll
        for (int ni = 0; ni < 8; ni++) {
            #pragma unroll
            for (int h = 0; h < 2; h++) {
                int row = row0 + wm + mi * 16 + r_ + h * 8;
                int col = col0 + wn + ni * 8 + c2;
                float v0 = acc[mi][ni][h * 2 + 0] + bias[col];
                float v1 = acc[mi][ni][h * 2 + 1] + bias[col + 1];
                if (EP == EP_GELU) {
                    v0 = 0.5f * v0 * (1.f + erff(v0 * 0.70710678118654752f));
                    v1 = 0.5f * v1 * (1.f + erff(v1 * 0.70710678118654752f));
                    *(uint32_t*)&Ch[(size_t)row * N + col] = packh2(v0, v1);
                } else if (EP == EP_RES) {
                    v0 += res[(size_t)row * N + col];
                    v1 += res[(size_t)row * N + col + 1];
                    *(float2*)&C[(size_t)row * N + col] = make_float2(v0, v1);
                } else if (EP == EP_HEADS) {
                    int mat = col >> 10;           // 0=Q,1=K,2=V (N=3072)
                    int cc  = col & 1023;
                    int bb = row >> 11, ss = row & 2047;
                    int hh = cc >> 6,  dd = cc & 63;
                    if (mat == 0) {                // Q pre-scaled by 1/8, [B,H,S,D]
                        *(uint32_t*)&Hq[(((size_t)(bb * Hc + hh)) * Sc + ss) * Dc + dd] =
                            packh2(v0 * 0.125f, v1 * 0.125f);
                    } else if (mat == 1) {         // K [B,H,S,D]
                        *(uint32_t*)&Hk[(((size_t)(bb * Hc + hh)) * Sc + ss) * Dc + dd] =
                            packh2(v0, v1);
                    } else {                       // V TRANSPOSED [B,H,D,S]
                        size_t base = ((size_t)(bb * Hc + hh)) * Dc;
                        Hv[(base + dd)     * Sc + ss] = __float2half_rn(v0);
                        Hv[(base + dd + 1) * Sc + ss] = __float2half_rn(v1);
                    }
                }
            }
        }
    }
}

// ---------------- fp16 TC flash attention: 64x64 tiles, 128 thr, cp.async KV ----------------
// All smem tiles: half, stored as half2 words, row stride LDW=36 words.
#define LDW 36
#define Q_WORDS  (64 * LDW)                     // 2304
#define KV_WORDS (2 * 64 * LDW)                 // K + V per stage: 4608
#define ATTN_SMEM ((Q_WORDS + 2*KV_WORDS + 64*LDW) * 4)   // 55296 bytes

__global__ void __launch_bounds__(128, 3) attn_tc(const __half* __restrict__ Q,
                                                  const __half* __restrict__ K,
                                                  const __half* __restrict__ V,
                                                  __half* __restrict__ ctx) {
    extern __shared__ uint32_t smu[];
    uint32_t smem_u = (uint32_t)__cvta_generic_to_shared(smu);
    uint32_t* Qs = smu;                          // [64][LDW]
    uint32_t* Ps = smu + Q_WORDS + 2 * KV_WORDS; // [64][LDW]

    int tid = threadIdx.x, lane = tid & 31, w = tid >> 5;
    int r_ = lane >> 2, c_ = lane & 3;
    int qt = (int)gridDim.x - 1 - (int)blockIdx.x;   // heavy tiles first
    int bh = blockIdx.y;
    int q0 = qt * 64;

    const __half* Qb = Q + (size_t)bh * Sc * Dc;
    const __half* Kb = K + (size_t)bh * Sc * Dc;
    const __half* Vb = V + (size_t)bh * Dc * Sc;     // transposed [D][S]

    // K tile [64 kv][64 d] halves; V tile [64 d][64 kv] halves (from transposed V)
    auto issue_kv = [&](int k0, int s) {
        uint32_t kbase = smem_u + (uint32_t)(Q_WORDS + s * KV_WORDS) * 4u;
        uint32_t vbase = kbase + (uint32_t)(64 * LDW) * 4u;
        #pragma unroll
        for (int it = 0; it < 4; it++) {
            int idx = tid + it * 128;
            int r = idx >> 3, wo = (idx & 7) * 4;    // 4 words = 8 halves
            cp16(kbase + (uint32_t)(r * LDW + wo) * 4u, Kb + (size_t)(k0 + r) * Dc + wo * 2);
            cp16(vbase + (uint32_t)(r * LDW + wo) * 4u, Vb + (size_t)r * Sc + k0 + wo * 2);
        }
        CP_COMMIT();
    };

    // Q tile copy + first KV (one group)
    {
        #pragma unroll
        for (int it = 0; it < 4; it++) {
            int idx = tid + it * 128;
            int r = idx >> 3, wo = (idx & 7) * 4;
            cp16(smem_u + (uint32_t)(r * LDW + wo) * 4u, Qb + (size_t)(q0 + r) * Dc + wo * 2);
        }
        issue_kv(0, 0);   // commits Q copies too
    }

    float o[8][4];
    #pragma unroll
    for (int nf = 0; nf < 8; nf++)
        #pragma unroll
        for (int q = 0; q < 4; q++) o[nf][q] = 0.f;
    float m0 = -1e30f, m1 = -1e30f, l0 = 0.f, l1 = 0.f;

    uint32_t qf[4][4];
    uint32_t* pw = Ps + w * 16 * LDW;
    int w16 = w * 16;

    for (int kt = 0; kt <= qt; kt++) {
        CP_WAIT0();
        __syncthreads();
        if (kt + 1 <= qt) issue_kv((kt + 1) * 64, (kt + 1) & 1);

        if (kt == 0) {    // load Q A-frags once (Q pre-scaled by 1/8 at producer)
            #pragma unroll
            for (int kc = 0; kc < 4; kc++) {
                int kb = kc * 8;
                qf[kc][0] = Qs[(w16 + r_) * LDW + kb + c_];
                qf[kc][1] = Qs[(w16 + r_ + 8) * LDW + kb + c_];
                qf[kc][2] = Qs[(w16 + r_) * LDW + kb + c_ + 4];
                qf[kc][3] = Qs[(w16 + r_ + 8) * LDW + kb + c_ + 4];
            }
        }

        const uint32_t* Ks = smu + Q_WORDS + (kt & 1) * KV_WORDS;
        const uint32_t* Vs = Ks + 64 * LDW;

        // ---- S = Q K^T (fp16 k16) ----
        float sacc[8][4];
        #pragma unroll
        for (int nf = 0; nf < 8; nf++)
            #pragma unroll
            for (int q = 0; q < 4; q++) sacc[nf][q] = 0.f;
        #pragma unroll
        for (int kc = 0; kc < 4; kc++) {
            int kb = kc * 8;
            #pragma unroll
            for (int nf = 0; nf < 8; nf++) {
                uint32_t b[2];
                b[0] = Ks[(nf * 8 + r_) * LDW + kb + c_];
                b[1] = Ks[(nf * 8 + r_) * LDW + kb + c_ + 4];
                mma16(sacc[nf], qf[kc], b);
            }
        }

        // ---- causal mask on diagonal tile (tile-relative) ----
        if (kt == qt) {
            int rr = w16 + r_;
            #pragma unroll
            for (int nf = 0; nf < 8; nf++) {
                int cb = nf * 8 + 2 * c_;
                if (cb     > rr)     sacc[nf][0] = -1e30f;
                if (cb + 1 > rr)     sacc[nf][1] = -1e30f;
                if (cb     > rr + 8) sacc[nf][2] = -1e30f;
                if (cb + 1 > rr + 8) sacc[nf][3] = -1e30f;
            }
        }

        // ---- online softmax ----
        float mx0 = -1e30f, mx1 = -1e30f;
        #pragma unroll
        for (int nf = 0; nf < 8; nf++) {
            mx0 = fmaxf(mx0, fmaxf(sacc[nf][0], sacc[nf][1]));
            mx1 = fmaxf(mx1, fmaxf(sacc[nf][2], sacc[nf][3]));
        }
        mx0 = fmaxf(mx0, __shfl_xor_sync(0xffffffffu, mx0, 1));
        mx0 = fmaxf(mx0, __shfl_xor_sync(0xffffffffu, mx0, 2));
        mx1 = fmaxf(mx1, __shfl_xor_sync(0xffffffffu, mx1, 1));
        mx1 = fmaxf(mx1, __shfl_xor_sync(0xffffffffu, mx1, 2));
        float mn0 = fmaxf(m0, mx0), mn1 = fmaxf(m1, mx1);
        float es0 = __expf(m0 - mn0), es1 = __expf(m1 - mn1);
        m0 = mn0; m1 = mn1;
        float ls0 = 0.f, ls1 = 0.f;
        #pragma unroll
        for (int nf = 0; nf < 8; nf++) {
            sacc[nf][0] = __expf(sacc[nf][0] - mn0);
            sacc[nf][1] = __expf(sacc[nf][1] - mn0);
            sacc[nf][2] = __expf(sacc[nf][2] - mn1);
            sacc[nf][3] = __expf(sacc[nf][3] - mn1);
            ls0 += sacc[nf][0] + sacc[nf][1];
            ls1 += sacc[nf][2] + sacc[nf][3];
        }
        ls0 += __shfl_xor_sync(0xffffffffu, ls0, 1);
        ls0 += __shfl_xor_sync(0xffffffffu, ls0, 2);
        ls1 += __shfl_xor_sync(0xffffffffu, ls1, 1);
        ls1 += __shfl_xor_sync(0xffffffffu, ls1, 2);
        l0 = l0 * es0 + ls0;
        l1 = l1 * es1 + ls1;
        #pragma unroll
        for (int nf = 0; nf < 8; nf++) {
            o[nf][0] *= es0; o[nf][1] *= es0;
            o[nf][2] *= es1; o[nf][3] *= es1;
        }

        // ---- P -> warp-private smem as half2 (C-frag pairs ARE k-pairs) ----
        #pragma unroll
        for (int nf = 0; nf < 8; nf++) {
            int wcol = nf * 4 + c_;
            pw[r_ * LDW + wcol]       = packh2(sacc[nf][0], sacc[nf][1]);
            pw[(r_ + 8) * LDW + wcol] = packh2(sacc[nf][2], sacc[nf][3]);
        }
        __syncwarp();

        // ---- O += P V (fp16 k16; V^T tile gives natural B-frags) ----
        #pragma unroll
        for (int kc = 0; kc < 4; kc++) {
            int kb = kc * 8;
            uint32_t af[4];
            af[0] = pw[r_ * LDW + kb + c_];
            af[1] = pw[(r_ + 8) * LDW + kb + c_];
            af[2] = pw[r_ * LDW + kb + c_ + 4];
            af[3] = pw[(r_ + 8) * LDW + kb + c_ + 4];
            #pragma unroll
            for (int nf = 0; nf < 8; nf++) {
                uint32_t b[2];
                b[0] = Vs[(nf * 8 + r_) * LDW + kb + c_];
                b[1] = Vs[(nf * 8 + r_) * LDW + kb + c_ + 4];
                mma16(o[nf], af, b);
            }
        }
        __syncwarp();
    }

    // ---- write ctx [B,S,E] as half ----
    int bb = bh >> 4, hh = bh & 15;
    int row0 = q0 + w16 + r_;
    float il0 = 1.f / l0, il1 = 1.f / l1;
    #pragma unroll
    for (int nf = 0; nf < 8; nf++) {
        int col = hh * 64 + nf * 8 + 2 * c_;
        *(uint32_t*)&ctx[((size_t)bb * Sc + row0) * Ec + col] =
            packh2(o[nf][0] * il0, o[nf][1] * il0);
        *(uint32_t*)&ctx[((size_t)bb * Sc + row0 + 8) * Ec + col] =
            packh2(o[nf][2] * il1, o[nf][3] * il1);
    }
}

// ---------------- launch ----------------
extern "C" void kernel_launch(void* const* d_in, const int* in_sizes, int n_in,
                              void* d_out, int out_size) {
    const float* x    = (const float*)d_in[0];
    const float* Wq   = (const float*)d_in[2];
    const float* bq   = (const float*)d_in[3];
    const float* Wk   = (const float*)d_in[4];
    const float* bk   = (const float*)d_in[5];
    const float* Wv   = (const float*)d_in[6];
    const float* bv   = (const float*)d_in[7];
    const float* Wo   = (const float*)d_in[8];
    const float* bo   = (const float*)d_in[9];
    const float* W1   = (const float*)d_in[10];
    const float* b1   = (const float*)d_in[11];
    const float* W2   = (const float*)d_in[12];
    const float* b2   = (const float*)d_in[13];
    const float* ln1g = (const float*)d_in[14];
    const float* ln1b = (const float*)d_in[15];
    const float* ln2g = (const float*)d_in[16];
    const float* ln2b = (const float*)d_in[17];
    float* out = (float*)d_out;

    __half *n_, *q_, *k_, *v_, *ctx_, *x2h_, *f1_;
    float *res_, *x2_, *bqkv_;
    uint32_t* wp_;
    cudaGetSymbolAddress((void**)&n_,   g_n);
    cudaGetSymbolAddress((void**)&q_,   g_q);
    cudaGetSymbolAddress((void**)&k_,   g_k);
    cudaGetSymbolAddress((void**)&v_,   g_v);
    cudaGetSymbolAddress((void**)&ctx_, g_ctx);
    cudaGetSymbolAddress((void**)&res_, g_res);
    cudaGetSymbolAddress((void**)&x2_,  g_x2);
    cudaGetSymbolAddress((void**)&x2h_, g_x2h);
    cudaGetSymbolAddress((void**)&f1_,  g_f1);
    cudaGetSymbolAddress((void**)&wp_,  g_wp);
    cudaGetSymbolAddress((void**)&bqkv_, g_bqkv);

    cudaFuncSetAttribute(hgemm<EP_HEADS>, cudaFuncAttributeMaxDynamicSharedMemorySize, TG_SMEM);
    cudaFuncSetAttribute(hgemm<EP_RES>,   cudaFuncAttributeMaxDynamicSharedMemorySize, TG_SMEM);
    cudaFuncSetAttribute(hgemm<EP_GELU>,  cudaFuncAttributeMaxDynamicSharedMemorySize, TG_SMEM);
    cudaFuncSetAttribute(attn_tc, cudaFuncAttributeMaxDynamicSharedMemorySize, ATTN_SMEM);

    // 0. convert + pack all weights to fp16 k-interleaved layout (one launch)
    long cblocks = ((WP_TOT + 3072) / 4 + 255) / 256;
    convert_all<<<(int)cblocks, 256>>>(Wq, Wk, Wv, Wo, W1, W2, bq, bk, bv, wp_, bqkv_);

    // 1. LN1 -> half (GEMM A only)
    ln_kernel<false, true><<<Mc, 256>>>(x, ln1g, ln1b, nullptr, n_);

    // 2. fused QKV projection (N=3072) -> Q(x0.125)/K half [B,H,S,D], V half [B,H,D,S]
    hgemm<EP_HEADS><<<dim3(3072/BN, Mc/BM), 256, TG_SMEM>>>(n_, wp_ + WP_QKV, bqkv_, nullptr,
                                                            nullptr, nullptr, q_, k_, v_,
                                                            Mc, 3072, Ec);

    // 3. flash attention (fp16 TC) -> ctx half [B,S,E]
    attn_tc<<<dim3(Sc/64, Bc*Hc), 128, ATTN_SMEM>>>(q_, k_, v_, ctx_);

    // 4. Wo projection + residual with x -> res fp32
    hgemm<EP_RES><<<dim3(Ec/BN, Mc/BM), 256, TG_SMEM>>>(ctx_, wp_ + WP_O, bo, x,
                                                        res_, nullptr, nullptr, nullptr, nullptr,
                                                        Mc, Ec, Ec);

    // 5. LN2 -> x2 fp32 (residual) + x2h half (GEMM A)
    ln_kernel<true, true><<<Mc, 256>>>(res_, ln2g, ln2b, x2_, x2h_);

    // 6. FFN1 + exact GELU -> f1 half
    hgemm<EP_GELU><<<dim3(Fc/BN, Mc/BM), 256, TG_SMEM>>>(x2h_, wp_ + WP_W1, b1, nullptr,
                                                         nullptr, f1_, nullptr, nullptr, nullptr,
                                                         Mc, Fc, Ec);

    // 7. FFN2 + bias + residual(x2) -> out fp32
    hgemm<EP_RES><<<dim3(Ec/BN, Mc/BM), 256, TG_SMEM>>>(f1_, wp_ + WP_W2, b2, x2_,
                                                        out, nullptr, nullptr, nullptr, nullptr,
                                                        Mc, Ec, Fc);
}